// round 8
// baseline (speedup 1.0000x reference)
#include <cuda_runtime.h>

#define UDIM 256
#define INDIM 128
#define BATCH 128
#define TLEN 1024
#define OUTD 400

// d_out layout: output [0,51200) | d_t [51200,83968) | gru1_h [83968,116736) | gru2_h [116736,149504)
#define OFF_DT   51200
#define OFF_G1   83968
#define OFF_G2   116736

#define LOG2E 1.4426950408889634f

typedef unsigned long long ull;

// scratch (no allocations allowed -> device globals)
__device__ float g_dt[BATCH * UDIM];
__device__ float g_query[BATCH * UDIM];
__device__ float g_ctx[BATCH * UDIM];
__device__ float g_W1t[UDIM * UDIM];   // W1 transposed: g_W1t[k][n] = W1[n][k]

// ---------------- low-level helpers ----------------
__device__ __forceinline__ ull pk2(float x, float y) {
    ull r; asm("mov.b64 %0, {%1, %2};" : "=l"(r) : "f"(x), "f"(y)); return r;
}
__device__ __forceinline__ float2 unpk(ull a) {
    float2 v; asm("mov.b64 {%0, %1}, %2;" : "=f"(v.x), "=f"(v.y) : "l"(a)); return v;
}
__device__ __forceinline__ void fma2(ull& d, ull a, ull b) {
    asm("fma.rn.f32x2 %0, %1, %2, %0;" : "+l"(d) : "l"(a), "l"(b));
}
__device__ __forceinline__ float ex2f(float x) {
    float r; asm("ex2.approx.f32 %0, %1;" : "=f"(r) : "f"(x)); return r;
}
__device__ __forceinline__ float rcpf(float x) {
    float r; asm("rcp.approx.f32 %0, %1;" : "=f"(r) : "f"(x)); return r;
}
__device__ __forceinline__ float tanh_f(float x) {
    float xc = fminf(fmaxf(x, -10.f), 10.f);
    float e = ex2f(xc * 2.885390081777927f);   // exp(2x)
    return (e - 1.f) * rcpf(e + 1.f);
}
__device__ __forceinline__ float sigm_f(float x) {
    float xc = fminf(fmaxf(x, -30.f), 30.f);
    float e = ex2f(-LOG2E * xc);
    return rcpf(1.f + e);
}

// ================= kT: one-time W1 transpose =================
// grid (8,8) x 256 threads; standard padded smem transpose.
__global__ __launch_bounds__(256) void kT_transpose(const float* __restrict__ W1) {
    __shared__ float ts[32][33];
    int bi = blockIdx.x, bj = blockIdx.y;
    int tx = threadIdx.x & 31, ty = threadIdx.x >> 5;   // ty 0..7
    #pragma unroll
    for (int i = 0; i < 32; i += 8)
        ts[ty + i][tx] = W1[(bi * 32 + ty + i) * UDIM + bj * 32 + tx];
    __syncthreads();
    #pragma unroll
    for (int i = 0; i < 32; i += 8)
        g_W1t[(bj * 32 + ty + i) * UDIM + bi * 32 + tx] = ts[tx][ty + i];
}

// ---------------- mv4b: batched matvec, 256 threads, 4 batches ----------------
#define WS2_STRIDE 36
#define WS2_HALF (256 * WS2_STRIDE)

__device__ __forceinline__ void mv4b(
    const float* __restrict__ W, int K,
    const float* __restrict__ i0, const float* __restrict__ i1,
    const float* __restrict__ i2, const float* __restrict__ i3,
    float* __restrict__ ws, int tid, float acc[4])
{
    int uu = tid >> 3, kc = tid & 7;   // staging: rows uu+32*it, k-chunk kc
    int nslices = K >> 5;
    float4 pf[8];
    #pragma unroll
    for (int it = 0; it < 8; it++)
        pf[it] = *(const float4*)(W + (uu + 32 * it) * K + kc * 4);

    for (int s = 0; s < nslices; s++) {
        float* wbuf = ws + (s & 1) * WS2_HALF;
        #pragma unroll
        for (int it = 0; it < 8; it++)
            *(float4*)(wbuf + (uu + 32 * it) * WS2_STRIDE + kc * 4) = pf[it];
        __syncthreads();
        if (s + 1 < nslices) {
            int ktn = (s + 1) << 5;
            #pragma unroll
            for (int it = 0; it < 8; it++)
                pf[it] = *(const float4*)(W + (uu + 32 * it) * K + ktn + kc * 4);
        }
        int kt = s << 5;
        const float* wrow = wbuf + tid * WS2_STRIDE;
        #pragma unroll
        for (int kk = 0; kk < 8; kk++) {
            float4 w  = *(const float4*)(wrow + kk * 4);
            float4 a0 = *(const float4*)(i0 + kt + kk * 4);
            float4 a1 = *(const float4*)(i1 + kt + kk * 4);
            float4 a2 = *(const float4*)(i2 + kt + kk * 4);
            float4 a3 = *(const float4*)(i3 + kt + kk * 4);
            acc[0] = fmaf(a0.x, w.x, fmaf(a0.y, w.y, fmaf(a0.z, w.z, fmaf(a0.w, w.w, acc[0]))));
            acc[1] = fmaf(a1.x, w.x, fmaf(a1.y, w.y, fmaf(a1.z, w.z, fmaf(a1.w, w.w, acc[1]))));
            acc[2] = fmaf(a2.x, w.x, fmaf(a2.y, w.y, fmaf(a2.z, w.z, fmaf(a2.w, w.w, acc[2]))));
            acc[3] = fmaf(a3.x, w.x, fmaf(a3.y, w.y, fmaf(a3.z, w.z, fmaf(a3.w, w.w, acc[3]))));
        }
    }
}

// ================= K0: attention GRU cell + query projection =================
#define K0_XS   0
#define K0_HS   (K0_XS + 4 * INDIM)
#define K0_DTS  (K0_HS + 4 * UDIM)
#define K0_WS   (K0_DTS + 4 * UDIM)
#define K0_SMEM_FLOATS (K0_WS + 2 * WS2_HALF)

__global__ __launch_bounds__(256) void k0_attn_gru(
    const float* __restrict__ x, const float* __restrict__ h,
    const float* __restrict__ Wih, const float* __restrict__ Whh,
    const float* __restrict__ bih, const float* __restrict__ bhh,
    const float* __restrict__ W2, float* __restrict__ out_dt)
{
    extern __shared__ float sm[];
    float* xs  = sm + K0_XS;
    float* hs  = sm + K0_HS;
    float* dts = sm + K0_DTS;
    float* ws  = sm + K0_WS;
    int u = threadIdx.x;
    int b0 = blockIdx.x * 4;

    for (int idx = u; idx < 4 * INDIM; idx += 256)
        xs[idx] = x[b0 * INDIM + idx];
    for (int idx = u; idx < 4 * UDIM; idx += 256)
        hs[idx] = h[b0 * UDIM + idx];
    // mv4b's first barrier orders these writes before any compute read.

    float gr[4], gz[4], gn[4], hr[4], hz[4], hn[4];
    {
        float br = bih[u], bz = bih[UDIM + u], bn = bih[2 * UDIM + u];
        float cr = bhh[u], cz = bhh[UDIM + u], cn = bhh[2 * UDIM + u];
        #pragma unroll
        for (int bb = 0; bb < 4; bb++) {
            gr[bb] = br; gz[bb] = bz; gn[bb] = bn;
            hr[bb] = cr; hz[bb] = cz; hn[bb] = cn;
        }
    }
    mv4b(Wih,                     INDIM, xs, xs + 128, xs + 256, xs + 384, ws, u, gr);
    mv4b(Wih + UDIM * INDIM,      INDIM, xs, xs + 128, xs + 256, xs + 384, ws, u, gz);
    mv4b(Wih + 2 * UDIM * INDIM,  INDIM, xs, xs + 128, xs + 256, xs + 384, ws, u, gn);
    mv4b(Whh,                     UDIM,  hs, hs + 256, hs + 512, hs + 768, ws, u, hr);
    mv4b(Whh + UDIM * UDIM,       UDIM,  hs, hs + 256, hs + 512, hs + 768, ws, u, hz);
    mv4b(Whh + 2 * UDIM * UDIM,   UDIM,  hs, hs + 256, hs + 512, hs + 768, ws, u, hn);

    #pragma unroll
    for (int bb = 0; bb < 4; bb++) {
        float r = sigm_f(gr[bb] + hr[bb]);
        float z = sigm_f(gz[bb] + hz[bb]);
        float n = tanh_f(gn[bb] + r * hn[bb]);
        float dv = (1.f - z) * n + z * hs[bb * 256 + u];
        dts[bb * 256 + u] = dv;
        int gi = (b0 + bb) * UDIM + u;
        g_dt[gi] = dv;
        out_dt[gi] = dv;
    }
    float q[4] = {0.f, 0.f, 0.f, 0.f};
    mv4b(W2, UDIM, dts, dts + 256, dts + 512, dts + 768, ws, u, q);
    #pragma unroll
    for (int bb = 0; bb < 4; bb++) g_query[(b0 + bb) * UDIM + u] = q[bb];
}

// ================= K1: fused keys-GEMM + tanh scores + online softmax + context =================
// 128 blocks (one per batch) x 512 threads (16 warps; warpR=wid>>1 0..7, warpC=wid&1 0..1).
// Warp tile 16 rows x 128 n. Thread: rows row0+rr (rr=0..3), n = nb..nb+15 as 8 (n,n+1) f32x2 accs.
// B operand: LDG.128 straight from pre-transposed g_W1t (no smem staging, no k-loop barriers).
#define MT_STRIDE 260
#define OFF_MT  0
#define OFF_SCP (128 * MT_STRIDE)          // 2 x 128 score partials
#define OFF_SC  (OFF_SCP + 256)
#define OFF_ES  (OFF_SC + 128)
#define OFF_ST  (OFF_ES + 128)
#define OFF_QS  (OFF_ST + 8)
#define OFF_VS  (OFF_QS + 256)
#define OFF_CTX (OFF_VS + 256)
#define K1_SMEM_FLOATS (OFF_CTX + 512)

__global__ __launch_bounds__(512, 1) void k1_attn(
    const float* __restrict__ memory, const float* __restrict__ vvec)
{
    extern __shared__ float sm[];
    float* Mt = sm + OFF_MT;
    float* scp = sm + OFF_SCP;
    float* scores_s = sm + OFF_SC;
    float* e_s = sm + OFF_ES;
    float* st = sm + OFF_ST;
    float* q_s = sm + OFF_QS;
    float* v_s = sm + OFF_VS;
    float* ctx_s = sm + OFF_CTX;

    int tid = threadIdx.x;
    int b = blockIdx.x;
    int wid = tid >> 5, lane = tid & 31;
    int warpR = wid >> 1, warpC = wid & 1;
    int r_l = lane >> 3, c_l = lane & 7;
    int row0 = warpR * 16 + r_l * 4;       // rows row0 + rr, rr=0..3
    int nb = warpC * 128 + c_l * 16;       // 16 consecutive n
    int uu = tid & 255, half = tid >> 8;

    for (int i = tid; i < 256; i += 512) {
        q_s[i] = g_query[b * UDIM + i];
        v_s[i] = vvec[i];
    }
    if (tid == 0) { st[0] = -1e30f; st[1] = 0.f; st[2] = 0.f; }

    float ctx = 0.f;
    float srun = 0.f;
    const float* memb = memory + (size_t)b * TLEN * UDIM;

    for (int tile = 0; tile < 8; tile++) {
        int t0 = tile * 128;
        __syncthreads();   // prev tile consumers done (incl. smem init on tile 0)
        // --- load Mt[128][256] (stride 260, float4 coalesced) ---
        #pragma unroll
        for (int it = 0; it < 16; it++) {
            int idx = tid + it * 512;
            int m = idx >> 6, q = idx & 63;
            float4 vld = *(const float4*)(memb + (size_t)(t0 + m) * UDIM + q * 4);
            *(float4*)(Mt + m * MT_STRIDE + q * 4) = vld;
        }
        __syncthreads();   // Mt visible to GEMM

        ull acc[4][8];
        #pragma unroll
        for (int rr = 0; rr < 4; rr++)
            #pragma unroll
            for (int j = 0; j < 8; j++) acc[rr][j] = 0ull;

        // --- GEMM: barrier-free k loop; B via LDG.128 from g_W1t, A via LDS broadcast ---
        const float* mrow = Mt + row0 * MT_STRIDE;
        const float* wt = g_W1t + nb;
        #pragma unroll 4
        for (int k = 0; k < 256; k++) {
            const longlong2* bp = (const longlong2*)(wt + k * UDIM);
            longlong2 q0 = bp[0], q1 = bp[1], q2 = bp[2], q3 = bp[3];
            #pragma unroll
            for (int rr = 0; rr < 4; rr++) {
                float a = mrow[rr * MT_STRIDE + k];
                ull pa = pk2(a, a);
                fma2(acc[rr][0], pa, (ull)q0.x);
                fma2(acc[rr][1], pa, (ull)q0.y);
                fma2(acc[rr][2], pa, (ull)q1.x);
                fma2(acc[rr][3], pa, (ull)q1.y);
                fma2(acc[rr][4], pa, (ull)q2.x);
                fma2(acc[rr][5], pa, (ull)q2.y);
                fma2(acc[rr][6], pa, (ull)q3.x);
                fma2(acc[rr][7], pa, (ull)q3.y);
            }
        }

        // --- scores epilogue: s_row = sum_n v[n]*tanh(key + q[n]) ---
        #pragma unroll
        for (int rr = 0; rr < 4; rr++) {
            float s = 0.f;
            #pragma unroll
            for (int j = 0; j < 8; j++) {
                float2 kv = unpk(acc[rr][j]);
                s = fmaf(v_s[nb + 2 * j],     tanh_f(kv.x + q_s[nb + 2 * j]),     s);
                s = fmaf(v_s[nb + 2 * j + 1], tanh_f(kv.y + q_s[nb + 2 * j + 1]), s);
            }
            #pragma unroll
            for (int off = 1; off <= 4; off <<= 1)
                s += __shfl_xor_sync(0xffffffffu, s, off);
            if (c_l == 0) scp[warpC * 128 + row0 + rr] = s;
        }
        __syncthreads();
        if (tid < 128) scores_s[tid] = scp[tid] + scp[128 + tid];
        __syncthreads();
        if (tid < 32) {
            float mx = fmaxf(fmaxf(scores_s[tid], scores_s[tid + 32]),
                             fmaxf(scores_s[tid + 64], scores_s[tid + 96]));
            #pragma unroll
            for (int off = 16; off > 0; off >>= 1)
                mx = fmaxf(mx, __shfl_xor_sync(0xffffffffu, mx, off));
            if (tid == 0) {
                float m_old = st[0];
                float m_new = fmaxf(m_old, mx);
                st[2] = ex2f((m_old - m_new) * LOG2E);
                st[0] = m_new;
            }
        }
        __syncthreads();
        float scale = st[2];
        float m_new = st[0];
        ctx *= scale;
        if (tid < 128) {
            float e = ex2f((scores_s[tid] - m_new) * LOG2E);
            e_s[tid] = e;
            srun = srun * scale + e;
        }
        __syncthreads();  // e_s ready

        // --- context accumulation: ctx[u] += sum_t e[t]*Mt[t][u] ---
        int tstart = half * 64;
        #pragma unroll 4
        for (int t = 0; t < 64; t++)
            ctx = fmaf(e_s[tstart + t], Mt[(tstart + t) * MT_STRIDE + uu], ctx);
    }

    __syncthreads();
    if (tid < 128) scores_s[tid] = srun;
    ctx_s[half * 256 + uu] = ctx;
    __syncthreads();
    if (tid < 32) {
        float s = scores_s[tid] + scores_s[tid + 32] + scores_s[tid + 64] + scores_s[tid + 96];
        #pragma unroll
        for (int off = 16; off > 0; off >>= 1)
            s += __shfl_xor_sync(0xffffffffu, s, off);
        if (tid == 0) st[1] = s;
    }
    __syncthreads();
    float rinv = 1.f / st[1];
    if (tid < 256) g_ctx[b * UDIM + tid] = (ctx_s[tid] + ctx_s[256 + tid]) * rinv;
}

// ================= K2: proj -> GRU1 -> GRU2 -> out =================
#define K2_CAT   0
#define K2_GI    (K2_CAT + 4 * 512)
#define K2_H1    (K2_GI + 4 * 256)
#define K2_H2    (K2_H1 + 4 * 256)
#define K2_G2IN  (K2_H2 + 4 * 256)
#define K2_BF    (K2_G2IN + 4 * 256)
#define K2_WS    (K2_BF + 4 * 256)
#define K2_SMEM_FLOATS (K2_WS + 2 * WS2_HALF)

__global__ __launch_bounds__(256) void k2_tail(
    const float* __restrict__ h1in, const float* __restrict__ h2in,
    const float* __restrict__ g1_Wih, const float* __restrict__ g1_Whh,
    const float* __restrict__ g1_bih, const float* __restrict__ g1_bhh,
    const float* __restrict__ g2_Wih, const float* __restrict__ g2_Whh,
    const float* __restrict__ g2_bih, const float* __restrict__ g2_bhh,
    const float* __restrict__ proj_W, const float* __restrict__ proj_b,
    const float* __restrict__ out_W, const float* __restrict__ out_b,
    float* __restrict__ out_all)
{
    extern __shared__ float sm[];
    float* cat  = sm + K2_CAT;
    float* gi   = sm + K2_GI;
    float* h1s  = sm + K2_H1;
    float* h2s  = sm + K2_H2;
    float* g2in = sm + K2_G2IN;
    float* bfs  = sm + K2_BF;
    float* ws   = sm + K2_WS;
    int u = threadIdx.x;
    int b0 = blockIdx.x * 4;

    for (int idx = u; idx < 4 * UDIM; idx += 256) {
        int bb = idx >> 8, j = idx & 255;
        cat[bb * 512 + j] = g_dt[(b0 + bb) * UDIM + j];
        cat[bb * 512 + UDIM + j] = g_ctx[(b0 + bb) * UDIM + j];
        h1s[bb * 256 + j] = h1in[(b0 + bb) * UDIM + j];
        h2s[bb * 256 + j] = h2in[(b0 + bb) * UDIM + j];
    }

    // ---- proj ----
    {
        float pb = proj_b[u];
        float a[4] = {pb, pb, pb, pb};
        mv4b(proj_W, 2 * UDIM, cat, cat + 512, cat + 1024, cat + 1536, ws, u, a);
        gi[u] = a[0]; gi[256 + u] = a[1]; gi[512 + u] = a[2]; gi[768 + u] = a[3];
    }

    // ---- GRU1 ----
    {
        float gr[4], gz[4], gn[4], hr[4], hz[4], hn[4];
        float br = g1_bih[u], bz = g1_bih[UDIM + u], bn = g1_bih[2 * UDIM + u];
        float cr = g1_bhh[u], cz = g1_bhh[UDIM + u], cn = g1_bhh[2 * UDIM + u];
        #pragma unroll
        for (int bb = 0; bb < 4; bb++) {
            gr[bb] = br; gz[bb] = bz; gn[bb] = bn;
            hr[bb] = cr; hz[bb] = cz; hn[bb] = cn;
        }
        mv4b(g1_Wih,                   UDIM, gi, gi + 256, gi + 512, gi + 768, ws, u, gr);
        mv4b(g1_Wih + UDIM * UDIM,     UDIM, gi, gi + 256, gi + 512, gi + 768, ws, u, gz);
        mv4b(g1_Wih + 2 * UDIM * UDIM, UDIM, gi, gi + 256, gi + 512, gi + 768, ws, u, gn);
        mv4b(g1_Whh,                   UDIM, h1s, h1s + 256, h1s + 512, h1s + 768, ws, u, hr);
        mv4b(g1_Whh + UDIM * UDIM,     UDIM, h1s, h1s + 256, h1s + 512, h1s + 768, ws, u, hz);
        mv4b(g1_Whh + 2 * UDIM * UDIM, UDIM, h1s, h1s + 256, h1s + 512, h1s + 768, ws, u, hn);
        #pragma unroll
        for (int bb = 0; bb < 4; bb++) {
            float r = sigm_f(gr[bb] + hr[bb]);
            float z = sigm_f(gz[bb] + hz[bb]);
            float n = tanh_f(gn[bb] + r * hn[bb]);
            float hnew = (1.f - z) * n + z * h1s[bb * 256 + u];
            out_all[OFF_G1 + (b0 + bb) * UDIM + u] = hnew;
            g2in[bb * 256 + u] = gi[bb * 256 + u] + hnew;
        }
    }

    // ---- GRU2 ----
    {
        float gr[4], gz[4], gn[4], hr[4], hz[4], hn[4];
        float br = g2_bih[u], bz = g2_bih[UDIM + u], bn = g2_bih[2 * UDIM + u];
        float cr = g2_bhh[u], cz = g2_bhh[UDIM + u], cn = g2_bhh[2 * UDIM + u];
        #pragma unroll
        for (int bb = 0; bb < 4; bb++) {
            gr[bb] = br; gz[bb] = bz; gn[bb] = bn;
            hr[bb] = cr; hz[bb] = cz; hn[bb] = cn;
        }
        mv4b(g2_Wih,                   UDIM, g2in, g2in + 256, g2in + 512, g2in + 768, ws, u, gr);
        mv4b(g2_Wih + UDIM * UDIM,     UDIM, g2in, g2in + 256, g2in + 512, g2in + 768, ws, u, gz);
        mv4b(g2_Wih + 2 * UDIM * UDIM, UDIM, g2in, g2in + 256, g2in + 512, g2in + 768, ws, u, gn);
        mv4b(g2_Whh,                   UDIM, h2s, h2s + 256, h2s + 512, h2s + 768, ws, u, hr);
        mv4b(g2_Whh + UDIM * UDIM,     UDIM, h2s, h2s + 256, h2s + 512, h2s + 768, ws, u, hz);
        mv4b(g2_Whh + 2 * UDIM * UDIM, UDIM, h2s, h2s + 256, h2s + 512, h2s + 768, ws, u, hn);
        #pragma unroll
        for (int bb = 0; bb < 4; bb++) {
            float r = sigm_f(gr[bb] + hr[bb]);
            float z = sigm_f(gz[bb] + hz[bb]);
            float n = tanh_f(gn[bb] + r * hn[bb]);
            float hnew = (1.f - z) * n + z * h2s[bb * 256 + u];
            out_all[OFF_G2 + (b0 + bb) * UDIM + u] = hnew;
            bfs[bb * 256 + u] = g2in[bb * 256 + u] + hnew;
        }
    }
    __syncthreads();

    // ---- output layer: [4 x 400] per-thread float4 streaming ----
    for (int o = u; o < OUTD; o += 256) {
        float ob = out_b[o];
        float a0 = ob, a1 = ob, a2 = ob, a3 = ob;
        const float4* w4 = (const float4*)(out_W + o * UDIM);
        #pragma unroll 8
        for (int j4 = 0; j4 < 64; j4++) {
            float4 w = w4[j4];
            int j = j4 * 4;
            a0 = fmaf(bfs[j], w.x, fmaf(bfs[j + 1], w.y, fmaf(bfs[j + 2], w.z, fmaf(bfs[j + 3], w.w, a0))));
            a1 = fmaf(bfs[256 + j], w.x, fmaf(bfs[257 + j], w.y, fmaf(bfs[258 + j], w.z, fmaf(bfs[259 + j], w.w, a1))));
            a2 = fmaf(bfs[512 + j], w.x, fmaf(bfs[513 + j], w.y, fmaf(bfs[514 + j], w.z, fmaf(bfs[515 + j], w.w, a2))));
            a3 = fmaf(bfs[768 + j], w.x, fmaf(bfs[769 + j], w.y, fmaf(bfs[770 + j], w.z, fmaf(bfs[771 + j], w.w, a3))));
        }
        out_all[(b0 + 0) * OUTD + o] = a0;
        out_all[(b0 + 1) * OUTD + o] = a1;
        out_all[(b0 + 2) * OUTD + o] = a2;
        out_all[(b0 + 3) * OUTD + o] = a3;
    }
}

extern "C" void kernel_launch(void* const* d_in, const int* in_sizes, int n_in,
                              void* d_out, int out_size) {
    const float* decoder_input = (const float*)d_in[0];
    const float* memory        = (const float*)d_in[1];
    const float* attn_hidden   = (const float*)d_in[2];
    const float* gru1_hidden   = (const float*)d_in[3];
    const float* gru2_hidden   = (const float*)d_in[4];
    const float* W1            = (const float*)d_in[5];
    const float* W2            = (const float*)d_in[6];
    const float* v             = (const float*)d_in[7];
    const float* attn_Wih      = (const float*)d_in[8];
    const float* attn_Whh      = (const float*)d_in[9];
    const float* attn_bih      = (const float*)d_in[10];
    const float* attn_bhh      = (const float*)d_in[11];
    const float* g1_Wih        = (const float*)d_in[12];
    const float* g1_Whh        = (const float*)d_in[13];
    const float* g1_bih        = (const float*)d_in[14];
    const float* g1_bhh        = (const float*)d_in[15];
    const float* g2_Wih        = (const float*)d_in[16];
    const float* g2_Whh        = (const float*)d_in[17];
    const float* g2_bih        = (const float*)d_in[18];
    const float* g2_bhh        = (const float*)d_in[19];
    const float* proj_W        = (const float*)d_in[20];
    const float* proj_b        = (const float*)d_in[21];
    const float* out_W         = (const float*)d_in[22];
    const float* out_b         = (const float*)d_in[23];
    float* out = (float*)d_out;

    int k0_smem = K0_SMEM_FLOATS * sizeof(float);
    int k1_smem = K1_SMEM_FLOATS * sizeof(float);
    int k2_smem = K2_SMEM_FLOATS * sizeof(float);
    cudaFuncSetAttribute(k0_attn_gru, cudaFuncAttributeMaxDynamicSharedMemorySize, k0_smem);
    cudaFuncSetAttribute(k1_attn, cudaFuncAttributeMaxDynamicSharedMemorySize, k1_smem);
    cudaFuncSetAttribute(k2_tail, cudaFuncAttributeMaxDynamicSharedMemorySize, k2_smem);

    kT_transpose<<<dim3(8, 8), 256>>>(W1);
    k0_attn_gru<<<32, 256, k0_smem>>>(decoder_input, attn_hidden,
                                      attn_Wih, attn_Whh, attn_bih, attn_bhh,
                                      W2, out + OFF_DT);
    k1_attn<<<128, 512, k1_smem>>>(memory, v);
    k2_tail<<<32, 256, k2_smem>>>(gru1_hidden, gru2_hidden,
                                  g1_Wih, g1_Whh, g1_bih, g1_bhh,
                                  g2_Wih, g2_Whh, g2_bih, g2_bhh,
                                  proj_W, proj_b, out_W, out_b, out);
}

// round 10
// speedup vs baseline: 5.2257x; 5.2257x over previous
#include <cuda_runtime.h>
#include <cuda_bf16.h>
#include <cstdint>

#define UDIM 256
#define INDIM 128
#define BATCH 128
#define TLEN 1024
#define OUTD 400
#define OFF_DT   51200
#define OFF_G1   83968
#define OFF_G2   116736
#define LOG2E 1.4426950408889634f

typedef unsigned long long ull;

__device__ float g_dt[BATCH * UDIM];
__device__ float g_query[BATCH * UDIM];
__device__ float g_ctx[BATCH * UDIM];
__device__ __nv_bfloat16 g_W1h[UDIM * UDIM];   // [n][k]
__device__ __nv_bfloat16 g_W1l[UDIM * UDIM];

__device__ __forceinline__ float ex2f(float x) {
    float r; asm("ex2.approx.f32 %0, %1;" : "=f"(r) : "f"(x)); return r;
}
__device__ __forceinline__ float rcpf(float x) {
    float r; asm("rcp.approx.f32 %0, %1;" : "=f"(r) : "f"(x)); return r;
}
__device__ __forceinline__ float tanh_f(float x) {
    float xc = fminf(fmaxf(x, -10.f), 10.f);
    float e = ex2f(xc * 2.885390081777927f);
    return (e - 1.f) * rcpf(e + 1.f);
}
__device__ __forceinline__ float sigm_f(float x) {
    float xc = fminf(fmaxf(x, -30.f), 30.f);
    float e = ex2f(-LOG2E * xc);
    return rcpf(1.f + e);
}
__device__ __forceinline__ uint32_t smem_u32(const void* p) {
    uint32_t a;
    asm("{ .reg .u64 t; cvta.to.shared.u64 t, %1; cvt.u32.u64 %0, t; }" : "=r"(a) : "l"(p));
    return a;
}
__device__ __forceinline__ void ldsm_x4(uint32_t r[4], uint32_t addr) {
    asm volatile("ldmatrix.sync.aligned.m8n8.x4.shared.b16 {%0,%1,%2,%3}, [%4];"
        : "=r"(r[0]), "=r"(r[1]), "=r"(r[2]), "=r"(r[3]) : "r"(addr));
}
__device__ __forceinline__ void mma_bf16(float d[4], const uint32_t a[4], const uint32_t b[2]) {
    asm volatile("mma.sync.aligned.m16n8k16.row.col.f32.bf16.bf16.f32 "
        "{%0,%1,%2,%3}, {%4,%5,%6,%7}, {%8,%9}, {%0,%1,%2,%3};"
        : "+f"(d[0]), "+f"(d[1]), "+f"(d[2]), "+f"(d[3])
        : "r"(a[0]), "r"(a[1]), "r"(a[2]), "r"(a[3]), "r"(b[0]), "r"(b[1]));
}

// ===== kW1prep: W1 fp32 -> bf16 hi/lo linear [n][k] (one-time) =====
__global__ __launch_bounds__(256) void kW1prep(const float* __restrict__ W1) {
    int idx = blockIdx.x * 256 + threadIdx.x;   // 65536 = n*256 + k
    float w = W1[idx];
    __nv_bfloat16 bh = __float2bfloat16(w);
    __nv_bfloat16 bl = __float2bfloat16(w - __bfloat162float(bh));
    g_W1h[idx] = bh;
    g_W1l[idx] = bl;
}

// ===== mv4b (unchanged) =====
#define WS2_STRIDE 36
#define WS2_HALF (256 * WS2_STRIDE)
__device__ __forceinline__ void mv4b(
    const float* __restrict__ W, int K,
    const float* __restrict__ i0, const float* __restrict__ i1,
    const float* __restrict__ i2, const float* __restrict__ i3,
    float* __restrict__ ws, int tid, float acc[4])
{
    int uu = tid >> 3, kc = tid & 7;
    int nslices = K >> 5;
    float4 pf[8];
    #pragma unroll
    for (int it = 0; it < 8; it++)
        pf[it] = *(const float4*)(W + (uu + 32 * it) * K + kc * 4);
    for (int s = 0; s < nslices; s++) {
        float* wbuf = ws + (s & 1) * WS2_HALF;
        #pragma unroll
        for (int it = 0; it < 8; it++)
            *(float4*)(wbuf + (uu + 32 * it) * WS2_STRIDE + kc * 4) = pf[it];
        __syncthreads();
        if (s + 1 < nslices) {
            int ktn = (s + 1) << 5;
            #pragma unroll
            for (int it = 0; it < 8; it++)
                pf[it] = *(const float4*)(W + (uu + 32 * it) * K + ktn + kc * 4);
        }
        int kt = s << 5;
        const float* wrow = wbuf + tid * WS2_STRIDE;
        #pragma unroll
        for (int kk = 0; kk < 8; kk++) {
            float4 w  = *(const float4*)(wrow + kk * 4);
            float4 a0 = *(const float4*)(i0 + kt + kk * 4);
            float4 a1 = *(const float4*)(i1 + kt + kk * 4);
            float4 a2 = *(const float4*)(i2 + kt + kk * 4);
            float4 a3 = *(const float4*)(i3 + kt + kk * 4);
            acc[0] = fmaf(a0.x, w.x, fmaf(a0.y, w.y, fmaf(a0.z, w.z, fmaf(a0.w, w.w, acc[0]))));
            acc[1] = fmaf(a1.x, w.x, fmaf(a1.y, w.y, fmaf(a1.z, w.z, fmaf(a1.w, w.w, acc[1]))));
            acc[2] = fmaf(a2.x, w.x, fmaf(a2.y, w.y, fmaf(a2.z, w.z, fmaf(a2.w, w.w, acc[2]))));
            acc[3] = fmaf(a3.x, w.x, fmaf(a3.y, w.y, fmaf(a3.z, w.z, fmaf(a3.w, w.w, acc[3]))));
        }
    }
}

// ===== K0 (unchanged from R5/874us baseline) =====
#define K0_XS   0
#define K0_HS   (K0_XS + 4 * INDIM)
#define K0_DTS  (K0_HS + 4 * UDIM)
#define K0_WS   (K0_DTS + 4 * UDIM)
#define K0_SMEM_FLOATS (K0_WS + 2 * WS2_HALF)
__global__ __launch_bounds__(256) void k0_attn_gru(
    const float* __restrict__ x, const float* __restrict__ h,
    const float* __restrict__ Wih, const float* __restrict__ Whh,
    const float* __restrict__ bih, const float* __restrict__ bhh,
    const float* __restrict__ W2, float* __restrict__ out_dt)
{
    extern __shared__ float sm[];
    float* xs = sm + K0_XS; float* hs = sm + K0_HS; float* dts = sm + K0_DTS; float* ws = sm + K0_WS;
    int u = threadIdx.x;
    int b0 = blockIdx.x * 4;
    for (int idx = u; idx < 4 * INDIM; idx += 256) xs[idx] = x[b0 * INDIM + idx];
    for (int idx = u; idx < 4 * UDIM; idx += 256)  hs[idx] = h[b0 * UDIM + idx];
    float gr[4], gz[4], gn[4], hr[4], hz[4], hn[4];
    {
        float br = bih[u], bz = bih[UDIM + u], bn = bih[2 * UDIM + u];
        float cr = bhh[u], cz = bhh[UDIM + u], cn = bhh[2 * UDIM + u];
        #pragma unroll
        for (int bb = 0; bb < 4; bb++) { gr[bb]=br; gz[bb]=bz; gn[bb]=bn; hr[bb]=cr; hz[bb]=cz; hn[bb]=cn; }
    }
    mv4b(Wih,                    INDIM, xs, xs+128, xs+256, xs+384, ws, u, gr);
    mv4b(Wih + UDIM*INDIM,       INDIM, xs, xs+128, xs+256, xs+384, ws, u, gz);
    mv4b(Wih + 2*UDIM*INDIM,     INDIM, xs, xs+128, xs+256, xs+384, ws, u, gn);
    mv4b(Whh,                    UDIM,  hs, hs+256, hs+512, hs+768, ws, u, hr);
    mv4b(Whh + UDIM*UDIM,        UDIM,  hs, hs+256, hs+512, hs+768, ws, u, hz);
    mv4b(Whh + 2*UDIM*UDIM,      UDIM,  hs, hs+256, hs+512, hs+768, ws, u, hn);
    #pragma unroll
    for (int bb = 0; bb < 4; bb++) {
        float r = sigm_f(gr[bb] + hr[bb]);
        float z = sigm_f(gz[bb] + hz[bb]);
        float n = tanh_f(gn[bb] + r * hn[bb]);
        float dv = (1.f - z) * n + z * hs[bb * 256 + u];
        dts[bb * 256 + u] = dv;
        int gi = (b0 + bb) * UDIM + u;
        g_dt[gi] = dv;
        out_dt[gi] = dv;
    }
    float q[4] = {0.f, 0.f, 0.f, 0.f};
    mv4b(W2, UDIM, dts, dts+256, dts+512, dts+768, ws, u, q);
    #pragma unroll
    for (int bb = 0; bb < 4; bb++) g_query[(b0 + bb) * UDIM + u] = q[bb];
}

// ===== K1: mma.sync bf16x3 keys-GEMM + tanh scores + online softmax + context =====
// 128 blocks x 512 threads (16 warps; warpM=wid&3 row-group of 32, warpN=wid>>2 col-group of 64).
// A padded [128][264] bf16 hi/lo (ldmatrix conflict-free); B chunk [256][88] bf16 hi/lo.
#define A_STRIDE_B 528
#define B_STRIDE_B 176
#define K1_SCORES 16
#define K1_SCP   528
#define K1_ES    2576
#define K1_QS    3088
#define K1_VS    4112
#define K1_AH    7168
#define K1_AL    74752
#define K1_BH    142336
#define K1_BL    187392
#define K1_SMEM  232448

__global__ __launch_bounds__(512, 1) void k1_mma(
    const float* __restrict__ memory, const float* __restrict__ vvec)
{
    extern __shared__ char smc[];
    float* st = (float*)(smc + 0);            // [0]=m_run [1]=sum [2]=scale
    float* scores_s = (float*)(smc + K1_SCORES);
    float* scp = (float*)(smc + K1_SCP);      // 512 partials
    float* e_s = (float*)(smc + K1_ES);
    float* q_s = (float*)(smc + K1_QS);
    float* v_s = (float*)(smc + K1_VS);
    float* ctx_s = (float*)(smc + K1_BH);     // alias over B region; used only at the end
    char* AH = smc + K1_AH;
    char* AL = smc + K1_AL;
    char* BH = smc + K1_BH;
    char* BL = smc + K1_BL;
    uint32_t sb = smem_u32(smc);

    int tid = threadIdx.x, b = blockIdx.x, wid = tid >> 5, lane = tid & 31;
    int warpM = wid & 3, warpN = wid >> 2;
    int uu = tid & 255, half = tid >> 8;
    // ldmatrix lane bases
    int m_lane = warpM * 32 + (lane & 7) + ((lane >> 3) & 1) * 8;
    int kA_off = (lane >> 4) * 8;
    uint32_t aBaseH = sb + K1_AH + m_lane * A_STRIDE_B + kA_off * 2;
    uint32_t aBaseL = aBaseH + (K1_AL - K1_AH);
    int n_lane = warpN * 64 + (lane & 7) + ((lane >> 4) & 1) * 8;
    int kB_off = ((lane >> 3) & 1) * 8;
    uint32_t bBaseH = sb + K1_BH + n_lane * B_STRIDE_B + kB_off * 2;
    uint32_t bBaseL = bBaseH + (K1_BL - K1_BH);

    for (int i = tid; i < 256; i += 512) { q_s[i] = g_query[b * UDIM + i]; v_s[i] = vvec[i]; }
    if (tid == 0) { st[0] = -1e30f; st[1] = 0.f; st[2] = 0.f; }

    float ctx = 0.f, srun = 0.f;
    const float* memb = memory + (size_t)b * TLEN * UDIM;

    for (int tile = 0; tile < 8; tile++) {
        __syncthreads();   // prev tile ctx reads of AH/AL done (and init sync)
        // --- stage A: fp32 -> bf16 hi/lo padded rows ---
        #pragma unroll
        for (int it = 0; it < 16; it++) {
            int idx = tid + it * 512;
            int t = idx >> 6, ug = idx & 63;
            float4 w = *(const float4*)(memb + (size_t)(tile * 128 + t) * UDIM + ug * 4);
            uint32_t h0, h1, l0, l1;
            asm("cvt.rn.bf16x2.f32 %0, %2, %1;" : "=r"(h0) : "f"(w.x), "f"(w.y));
            asm("cvt.rn.bf16x2.f32 %0, %2, %1;" : "=r"(h1) : "f"(w.z), "f"(w.w));
            float rx = w.x - __uint_as_float(h0 << 16);
            float ry = w.y - __uint_as_float(h0 & 0xffff0000u);
            float rz = w.z - __uint_as_float(h1 << 16);
            float rw = w.w - __uint_as_float(h1 & 0xffff0000u);
            asm("cvt.rn.bf16x2.f32 %0, %2, %1;" : "=r"(l0) : "f"(rx), "f"(ry));
            asm("cvt.rn.bf16x2.f32 %0, %2, %1;" : "=r"(l1) : "f"(rz), "f"(rw));
            int off = t * A_STRIDE_B + ug * 8;
            *(uint2*)(AH + off) = make_uint2(h0, h1);
            *(uint2*)(AL + off) = make_uint2(l0, l1);
        }

        float acc[2][8][4];
        #pragma unroll
        for (int mi = 0; mi < 2; mi++)
            #pragma unroll
            for (int nj = 0; nj < 8; nj++)
                #pragma unroll
                for (int r = 0; r < 4; r++) acc[mi][nj][r] = 0.f;

        for (int c = 0; c < 4; c++) {
            __syncthreads();   // prev chunk B reads done; A stores visible (c==0)
            // --- stage B chunk hi/lo ---
            #pragma unroll
            for (int it = 0; it < 4; it++) {
                int idx = tid + it * 512;
                int n = idx >> 3, kg = idx & 7;
                uint4 vh = *(const uint4*)((const char*)g_W1h + n * 512 + c * 128 + kg * 16);
                uint4 vl = *(const uint4*)((const char*)g_W1l + n * 512 + c * 128 + kg * 16);
                *(uint4*)(BH + n * B_STRIDE_B + kg * 16) = vh;
                *(uint4*)(BL + n * B_STRIDE_B + kg * 16) = vl;
            }
            __syncthreads();
            // --- 4 k16 steps ---
            #pragma unroll
            for (int ks = 0; ks < 4; ks++) {
                int kg2 = (c * 64 + ks * 16) * 2;
                uint32_t bfr[8][2], ah[2][4], al[2][4];
                #pragma unroll
                for (int ng = 0; ng < 4; ng++) {
                    uint32_t r[4];
                    ldsm_x4(r, bBaseH + ng * (16 * B_STRIDE_B) + ks * 32);
                    bfr[2*ng][0] = r[0]; bfr[2*ng][1] = r[1];
                    bfr[2*ng+1][0] = r[2]; bfr[2*ng+1][1] = r[3];
                }
                ldsm_x4(ah[0], aBaseH + kg2);
                ldsm_x4(ah[1], aBaseH + kg2 + 16 * A_STRIDE_B);
                #pragma unroll
                for (int mi = 0; mi < 2; mi++)
                    #pragma unroll
                    for (int nj = 0; nj < 8; nj++) mma_bf16(acc[mi][nj], ah[mi], bfr[nj]);
                ldsm_x4(al[0], aBaseL + kg2);
                ldsm_x4(al[1], aBaseL + kg2 + 16 * A_STRIDE_B);
                #pragma unroll
                for (int mi = 0; mi < 2; mi++)
                    #pragma unroll
                    for (int nj = 0; nj < 8; nj++) mma_bf16(acc[mi][nj], al[mi], bfr[nj]);
                #pragma unroll
                for (int ng = 0; ng < 4; ng++) {
                    uint32_t r[4];
                    ldsm_x4(r, bBaseL + ng * (16 * B_STRIDE_B) + ks * 32);
                    bfr[2*ng][0] = r[0]; bfr[2*ng][1] = r[1];
                    bfr[2*ng+1][0] = r[2]; bfr[2*ng+1][1] = r[3];
                }
                #pragma unroll
                for (int mi = 0; mi < 2; mi++)
                    #pragma unroll
                    for (int nj = 0; nj < 8; nj++) mma_bf16(acc[mi][nj], ah[mi], bfr[nj]);
            }
        }

        // --- scores epilogue ---
        {
            int lq = lane >> 2, lr = lane & 3;
            #pragma unroll
            for (int mi = 0; mi < 2; mi++) {
                float s0 = 0.f, s1 = 0.f;
                #pragma unroll
                for (int nj = 0; nj < 8; nj++) {
                    int n0 = warpN * 64 + nj * 8 + lr * 2;
                    float q0 = q_s[n0], q1 = q_s[n0 + 1];
                    float v0 = v_s[n0], v1 = v_s[n0 + 1];
                    s0 = fmaf(v0, tanh_f(acc[mi][nj][0] + q0), s0);
                    s0 = fmaf(v1, tanh_f(acc[mi][nj][1] + q1), s0);
                    s1 = fmaf(v0, tanh_f(acc[mi][nj][2] + q0), s1);
                    s1 = fmaf(v1, tanh_f(acc[mi][nj][3] + q1), s1);
                }
                s0 += __shfl_xor_sync(0xffffffffu, s0, 1);
                s0 += __shfl_xor_sync(0xffffffffu, s0, 2);
                s1 += __shfl_xor_sync(0xffffffffu, s1, 1);
                s1 += __shfl_xor_sync(0xffffffffu, s1, 2);
                if (lr == 0) {
                    int r0 = warpM * 32 + mi * 16 + lq;
                    scp[warpN * 128 + r0] = s0;
                    scp[warpN * 128 + r0 + 8] = s1;
                }
            }
        }
        __syncthreads();
        if (tid < 128)
            scores_s[tid] = (scp[tid] + scp[128 + tid]) + (scp[256 + tid] + scp[384 + tid]);
        __syncthreads();
        if (tid < 32) {
            float mx = fmaxf(fmaxf(scores_s[tid], scores_s[tid + 32]),
                             fmaxf(scores_s[tid + 64], scores_s[tid + 96]));
            #pragma unroll
            for (int off = 16; off > 0; off >>= 1)
                mx = fmaxf(mx, __shfl_xor_sync(0xffffffffu, mx, off));
            if (tid == 0) {
                float m_old = st[0];
                float m_new = fmaxf(m_old, mx);
                st[2] = ex2f((m_old - m_new) * LOG2E);
                st[0] = m_new;
            }
        }
        __syncthreads();
        float scale = st[2];
        float m_new = st[0];
        ctx *= scale;
        if (tid < 128) {
            float e = ex2f((scores_s[tid] - m_new) * LOG2E);
            e_s[tid] = e;
            srun = srun * scale + e;
        }
        __syncthreads();
        // --- context: ctx[u] += sum_t e[t] * (AH[t][u] + AL[t][u]) ---
        int tstart = half * 64;
        #pragma unroll 4
        for (int t = 0; t < 64; t++) {
            int tt = tstart + t;
            int off = tt * A_STRIDE_B + uu * 2;
            unsigned short ha = *(unsigned short*)(AH + off);
            unsigned short la = *(unsigned short*)(AL + off);
            float a = __uint_as_float(((uint32_t)ha) << 16) + __uint_as_float(((uint32_t)la) << 16);
            ctx = fmaf(e_s[tt], a, ctx);
        }
    }

    __syncthreads();
    if (tid < 128) scores_s[tid] = srun;
    ctx_s[half * 256 + uu] = ctx;
    __syncthreads();
    if (tid < 32) {
        float s = scores_s[tid] + scores_s[tid + 32] + scores_s[tid + 64] + scores_s[tid + 96];
        #pragma unroll
        for (int off = 16; off > 0; off >>= 1)
            s += __shfl_xor_sync(0xffffffffu, s, off);
        if (tid == 0) st[1] = s;
    }
    __syncthreads();
    float rinv = 1.f / st[1];
    if (tid < 256) g_ctx[b * UDIM + tid] = (ctx_s[tid] + ctx_s[256 + tid]) * rinv;
}

// ===== K2 (unchanged from R5/874us baseline) =====
#define K2_CAT   0
#define K2_GI    (K2_CAT + 4 * 512)
#define K2_H1    (K2_GI + 4 * 256)
#define K2_H2    (K2_H1 + 4 * 256)
#define K2_G2IN  (K2_H2 + 4 * 256)
#define K2_BF    (K2_G2IN + 4 * 256)
#define K2_WS    (K2_BF + 4 * 256)
#define K2_SMEM_FLOATS (K2_WS + 2 * WS2_HALF)
__global__ __launch_bounds__(256) void k2_tail(
    const float* __restrict__ h1in, const float* __restrict__ h2in,
    const float* __restrict__ g1_Wih, const float* __restrict__ g1_Whh,
    const float* __restrict__ g1_bih, const float* __restrict__ g1_bhh,
    const float* __restrict__ g2_Wih, const float* __restrict__ g2_Whh,
    const float* __restrict__ g2_bih, const float* __restrict__ g2_bhh,
    const float* __restrict__ proj_W, const float* __restrict__ proj_b,
    const float* __restrict__ out_W, const float* __restrict__ out_b,
    float* __restrict__ out_all)
{
    extern __shared__ float sm[];
    float* cat = sm + K2_CAT; float* gi = sm + K2_GI; float* h1s = sm + K2_H1; float* h2s = sm + K2_H2;
    float* g2in = sm + K2_G2IN; float* bfs = sm + K2_BF; float* ws = sm + K2_WS;
    int u = threadIdx.x;
    int b0 = blockIdx.x * 4;
    for (int idx = u; idx < 4 * UDIM; idx += 256) {
        int bb = idx >> 8, j = idx & 255;
        cat[bb * 512 + j] = g_dt[(b0 + bb) * UDIM + j];
        cat[bb * 512 + UDIM + j] = g_ctx[(b0 + bb) * UDIM + j];
        h1s[bb * 256 + j] = h1in[(b0 + bb) * UDIM + j];
        h2s[bb * 256 + j] = h2in[(b0 + bb) * UDIM + j];
    }
    {
        float pb = proj_b[u];
        float a[4] = {pb, pb, pb, pb};
        mv4b(proj_W, 2 * UDIM, cat, cat + 512, cat + 1024, cat + 1536, ws, u, a);
        gi[u] = a[0]; gi[256 + u] = a[1]; gi[512 + u] = a[2]; gi[768 + u] = a[3];
    }
    {
        float gr[4], gz[4], gn[4], hr[4], hz[4], hn[4];
        float br = g1_bih[u], bz = g1_bih[UDIM + u], bn = g1_bih[2 * UDIM + u];
        float cr = g1_bhh[u], cz = g1_bhh[UDIM + u], cn = g1_bhh[2 * UDIM + u];
        #pragma unroll
        for (int bb = 0; bb < 4; bb++) { gr[bb]=br; gz[bb]=bz; gn[bb]=bn; hr[bb]=cr; hz[bb]=cz; hn[bb]=cn; }
        mv4b(g1_Wih,                 UDIM, gi, gi+256, gi+512, gi+768, ws, u, gr);
        mv4b(g1_Wih + UDIM*UDIM,     UDIM, gi, gi+256, gi+512, gi+768, ws, u, gz);
        mv4b(g1_Wih + 2*UDIM*UDIM,   UDIM, gi, gi+256, gi+512, gi+768, ws, u, gn);
        mv4b(g1_Whh,                 UDIM, h1s, h1s+256, h1s+512, h1s+768, ws, u, hr);
        mv4b(g1_Whh + UDIM*UDIM,     UDIM, h1s, h1s+256, h1s+512, h1s+768, ws, u, hz);
        mv4b(g1_Whh + 2*UDIM*UDIM,   UDIM, h1s, h1s+256, h1s+512, h1s+768, ws, u, hn);
        #pragma unroll
        for (int bb = 0; bb < 4; bb++) {
            float r = sigm_f(gr[bb] + hr[bb]);
            float z = sigm_f(gz[bb] + hz[bb]);
            float n = tanh_f(gn[bb] + r * hn[bb]);
            float hnew = (1.f - z) * n + z * h1s[bb * 256 + u];
            out_all[OFF_G1 + (b0 + bb) * UDIM + u] = hnew;
            g2in[bb * 256 + u] = gi[bb * 256 + u] + hnew;
        }
    }
    {
        float gr[4], gz[4], gn[4], hr[4], hz[4], hn[4];
        float br = g2_bih[u], bz = g2_bih[UDIM + u], bn = g2_bih[2 * UDIM + u];
        float cr = g2_bhh[u], cz = g2_bhh[UDIM + u], cn = g2_bhh[2 * UDIM + u];
        #pragma unroll
        for (int bb = 0; bb < 4; bb++) { gr[bb]=br; gz[bb]=bz; gn[bb]=bn; hr[bb]=cr; hz[bb]=cz; hn[bb]=cn; }
        mv4b(g2_Wih,                 UDIM, g2in, g2in+256, g2in+512, g2in+768, ws, u, gr);
        mv4b(g2_Wih + UDIM*UDIM,     UDIM, g2in, g2in+256, g2in+512, g2in+768, ws, u, gz);
        mv4b(g2_Wih + 2*UDIM*UDIM,   UDIM, g2in, g2in+256, g2in+512, g2in+768, ws, u, gn);
        mv4b(g2_Whh,                 UDIM, h2s, h2s+256, h2s+512, h2s+768, ws, u, hr);
        mv4b(g2_Whh + UDIM*UDIM,     UDIM, h2s, h2s+256, h2s+512, h2s+768, ws, u, hz);
        mv4b(g2_Whh + 2*UDIM*UDIM,   UDIM, h2s, h2s+256, h2s+512, h2s+768, ws, u, hn);
        #pragma unroll
        for (int bb = 0; bb < 4; bb++) {
            float r = sigm_f(gr[bb] + hr[bb]);
            float z = sigm_f(gz[bb] + hz[bb]);
            float n = tanh_f(gn[bb] + r * hn[bb]);
            float hnew = (1.f - z) * n + z * h2s[bb * 256 + u];
            out_all[OFF_G2 + (b0 + bb) * UDIM + u] = hnew;
            bfs[bb * 256 + u] = g2in[bb * 256 + u] + hnew;
        }
    }
    __syncthreads();
    for (int o = u; o < OUTD; o += 256) {
        float ob = out_b[o];
        float a0 = ob, a1 = ob, a2 = ob, a3 = ob;
        const float4* w4 = (const float4*)(out_W + o * UDIM);
        #pragma unroll 8
        for (int j4 = 0; j4 < 64; j4++) {
            float4 w = w4[j4];
            int j = j4 * 4;
            a0 = fmaf(bfs[j], w.x, fmaf(bfs[j+1], w.y, fmaf(bfs[j+2], w.z, fmaf(bfs[j+3], w.w, a0))));
            a1 = fmaf(bfs[256+j], w.x, fmaf(bfs[257+j], w.y, fmaf(bfs[258+j], w.z, fmaf(bfs[259+j], w.w, a1))));
            a2 = fmaf(bfs[512+j], w.x, fmaf(bfs[513+j], w.y, fmaf(bfs[514+j], w.z, fmaf(bfs[515+j], w.w, a2))));
            a3 = fmaf(bfs[768+j], w.x, fmaf(bfs[769+j], w.y, fmaf(bfs[770+j], w.z, fmaf(bfs[771+j], w.w, a3))));
        }
        out_all[(b0 + 0) * OUTD + o] = a0;
        out_all[(b0 + 1) * OUTD + o] = a1;
        out_all[(b0 + 2) * OUTD + o] = a2;
        out_all[(b0 + 3) * OUTD + o] = a3;
    }
}

extern "C" void kernel_launch(void* const* d_in, const int* in_sizes, int n_in,
                              void* d_out, int out_size) {
    const float* decoder_input = (const float*)d_in[0];
    const float* memory        = (const float*)d_in[1];
    const float* attn_hidden   = (const float*)d_in[2];
    const float* gru1_hidden   = (const float*)d_in[3];
    const float* gru2_hidden   = (const float*)d_in[4];
    const float* W1            = (const float*)d_in[5];
    const float* W2            = (const float*)d_in[6];
    const float* v             = (const float*)d_in[7];
    const float* attn_Wih      = (const float*)d_in[8];
    const float* attn_Whh      = (const float*)d_in[9];
    const float* attn_bih      = (const float*)d_in[10];
    const float* attn_bhh      = (const float*)d_in[11];
    const float* g1_Wih        = (const float*)d_in[12];
    const float* g1_Whh        = (const float*)d_in[13];
    const float* g1_bih        = (const float*)d_in[14];
    const float* g1_bhh        = (const float*)d_in[15];
    const float* g2_Wih        = (const float*)d_in[16];
    const float* g2_Whh        = (const float*)d_in[17];
    const float* g2_bih        = (const float*)d_in[18];
    const float* g2_bhh        = (const float*)d_in[19];
    const float* proj_W        = (const float*)d_in[20];
    const float* proj_b        = (const float*)d_in[21];
    const float* out_W         = (const float*)d_in[22];
    const float* out_b         = (const float*)d_in[23];
    float* out = (float*)d_out;

    int k0_smem = K0_SMEM_FLOATS * sizeof(float);
    int k2_smem = K2_SMEM_FLOATS * sizeof(float);
    cudaFuncSetAttribute(k0_attn_gru, cudaFuncAttributeMaxDynamicSharedMemorySize, k0_smem);
    cudaFuncSetAttribute(k1_mma, cudaFuncAttributeMaxDynamicSharedMemorySize, K1_SMEM);
    cudaFuncSetAttribute(k2_tail, cudaFuncAttributeMaxDynamicSharedMemorySize, k2_smem);

    kW1prep<<<256, 256>>>(W1);
    k0_attn_gru<<<32, 256, k0_smem>>>(decoder_input, attn_hidden,
                                      attn_Wih, attn_Whh, attn_bih, attn_bhh,
                                      W2, out + OFF_DT);
    k1_mma<<<128, 512, K1_SMEM>>>(memory, v);
    k2_tail<<<32, 256, k2_smem>>>(gru1_hidden, gru2_hidden,
                                  g1_Wih, g1_Whh, g1_bih, g1_bhh,
                                  g2_Wih, g2_Whh, g2_bih, g2_bhh,
                                  proj_W, proj_b, out_W, out_b, out);
}

// round 13
// speedup vs baseline: 6.0362x; 1.1551x over previous
#include <cuda_runtime.h>
#include <cuda_fp16.h>
#include <cstdint>

#define UDIM 256
#define INDIM 128
#define BATCH 128
#define TLEN 1024
#define OUTD 400
#define OFF_DT   51200
#define OFF_G1   83968
#define OFF_G2   116736
#define LOG2E 1.4426950408889634f

typedef unsigned long long ull;

__device__ float g_dt[BATCH * UDIM];
__device__ float g_query[BATCH * UDIM];
__device__ float g_ctx[BATCH * UDIM];
__device__ __align__(16) __half g_W1f[UDIM * UDIM];   // [n][k] fp16

__device__ __forceinline__ float ex2f(float x) {
    float r; asm("ex2.approx.f32 %0, %1;" : "=f"(r) : "f"(x)); return r;
}
__device__ __forceinline__ float rcpf(float x) {
    float r; asm("rcp.approx.f32 %0, %1;" : "=f"(r) : "f"(x)); return r;
}
__device__ __forceinline__ float tanh_f(float x) {
    float xc = fminf(fmaxf(x, -10.f), 10.f);
    float e = ex2f(xc * 2.885390081777927f);
    return (e - 1.f) * rcpf(e + 1.f);
}
__device__ __forceinline__ float sigm_f(float x) {
    float xc = fminf(fmaxf(x, -30.f), 30.f);
    float e = ex2f(-LOG2E * xc);
    return rcpf(1.f + e);
}
__device__ __forceinline__ uint32_t smem_u32(const void* p) {
    uint32_t a;
    asm("{ .reg .u64 t; cvta.to.shared.u64 t, %1; cvt.u32.u64 %0, t; }" : "=r"(a) : "l"(p));
    return a;
}
__device__ __forceinline__ void ldsm_x4(uint32_t r[4], uint32_t addr) {
    asm volatile("ldmatrix.sync.aligned.m8n8.x4.shared.b16 {%0,%1,%2,%3}, [%4];"
        : "=r"(r[0]), "=r"(r[1]), "=r"(r[2]), "=r"(r[3]) : "r"(addr));
}
__device__ __forceinline__ void mma_f16(float d[4], const uint32_t a[4], const uint32_t b[2]) {
    asm volatile("mma.sync.aligned.m16n8k16.row.col.f32.f16.f16.f32 "
        "{%0,%1,%2,%3}, {%4,%5,%6,%7}, {%8,%9}, {%0,%1,%2,%3};"
        : "+f"(d[0]), "+f"(d[1]), "+f"(d[2]), "+f"(d[3])
        : "r"(a[0]), "r"(a[1]), "r"(a[2]), "r"(a[3]), "r"(b[0]), "r"(b[1]));
}

// ===== kW1prep: W1 fp32 -> fp16 linear [n][k] (one-time) =====
__global__ __launch_bounds__(256) void kW1prep(const float* __restrict__ W1) {
    int idx = blockIdx.x * 256 + threadIdx.x;   // 65536
    g_W1f[idx] = __float2half_rn(W1[idx]);
}

// ===== mv4b (unchanged; proven) =====
#define WS2_STRIDE 36
#define WS2_HALF (256 * WS2_STRIDE)
__device__ __forceinline__ void mv4b(
    const float* __restrict__ W, int K,
    const float* __restrict__ i0, const float* __restrict__ i1,
    const float* __restrict__ i2, const float* __restrict__ i3,
    float* __restrict__ ws, int tid, float acc[4])
{
    int uu = tid >> 3, kc = tid & 7;
    int nslices = K >> 5;
    float4 pf[8];
    #pragma unroll
    for (int it = 0; it < 8; it++)
        pf[it] = *(const float4*)(W + (uu + 32 * it) * K + kc * 4);
    for (int s = 0; s < nslices; s++) {
        float* wbuf = ws + (s & 1) * WS2_HALF;
        #pragma unroll
        for (int it = 0; it < 8; it++)
            *(float4*)(wbuf + (uu + 32 * it) * WS2_STRIDE + kc * 4) = pf[it];
        __syncthreads();
        if (s + 1 < nslices) {
            int ktn = (s + 1) << 5;
            #pragma unroll
            for (int it = 0; it < 8; it++)
                pf[it] = *(const float4*)(W + (uu + 32 * it) * K + ktn + kc * 4);
        }
        int kt = s << 5;
        const float* wrow = wbuf + tid * WS2_STRIDE;
        #pragma unroll
        for (int kk = 0; kk < 8; kk++) {
            float4 w  = *(const float4*)(wrow + kk * 4);
            float4 a0 = *(const float4*)(i0 + kt + kk * 4);
            float4 a1 = *(const float4*)(i1 + kt + kk * 4);
            float4 a2 = *(const float4*)(i2 + kt + kk * 4);
            float4 a3 = *(const float4*)(i3 + kt + kk * 4);
            acc[0] = fmaf(a0.x, w.x, fmaf(a0.y, w.y, fmaf(a0.z, w.z, fmaf(a0.w, w.w, acc[0]))));
            acc[1] = fmaf(a1.x, w.x, fmaf(a1.y, w.y, fmaf(a1.z, w.z, fmaf(a1.w, w.w, acc[1]))));
            acc[2] = fmaf(a2.x, w.x, fmaf(a2.y, w.y, fmaf(a2.z, w.z, fmaf(a2.w, w.w, acc[2]))));
            acc[3] = fmaf(a3.x, w.x, fmaf(a3.y, w.y, fmaf(a3.z, w.z, fmaf(a3.w, w.w, acc[3]))));
        }
    }
}

// ===== K0 (unchanged; proven) =====
#define K0_XS   0
#define K0_HS   (K0_XS + 4 * INDIM)
#define K0_DTS  (K0_HS + 4 * UDIM)
#define K0_WS   (K0_DTS + 4 * UDIM)
#define K0_SMEM_FLOATS (K0_WS + 2 * WS2_HALF)
__global__ __launch_bounds__(256) void k0_attn_gru(
    const float* __restrict__ x, const float* __restrict__ h,
    const float* __restrict__ Wih, const float* __restrict__ Whh,
    const float* __restrict__ bih, const float* __restrict__ bhh,
    const float* __restrict__ W2, float* __restrict__ out_dt)
{
    extern __shared__ float sm[];
    float* xs = sm + K0_XS; float* hs = sm + K0_HS; float* dts = sm + K0_DTS; float* ws = sm + K0_WS;
    int u = threadIdx.x;
    int b0 = blockIdx.x * 4;
    for (int idx = u; idx < 4 * INDIM; idx += 256) xs[idx] = x[b0 * INDIM + idx];
    for (int idx = u; idx < 4 * UDIM; idx += 256)  hs[idx] = h[b0 * UDIM + idx];
    float gr[4], gz[4], gn[4], hr[4], hz[4], hn[4];
    {
        float br = bih[u], bz = bih[UDIM + u], bn = bih[2 * UDIM + u];
        float cr = bhh[u], cz = bhh[UDIM + u], cn = bhh[2 * UDIM + u];
        #pragma unroll
        for (int bb = 0; bb < 4; bb++) { gr[bb]=br; gz[bb]=bz; gn[bb]=bn; hr[bb]=cr; hz[bb]=cz; hn[bb]=cn; }
    }
    mv4b(Wih,                    INDIM, xs, xs+128, xs+256, xs+384, ws, u, gr);
    mv4b(Wih + UDIM*INDIM,       INDIM, xs, xs+128, xs+256, xs+384, ws, u, gz);
    mv4b(Wih + 2*UDIM*INDIM,     INDIM, xs, xs+128, xs+256, xs+384, ws, u, gn);
    mv4b(Whh,                    UDIM,  hs, hs+256, hs+512, hs+768, ws, u, hr);
    mv4b(Whh + UDIM*UDIM,        UDIM,  hs, hs+256, hs+512, hs+768, ws, u, hz);
    mv4b(Whh + 2*UDIM*UDIM,      UDIM,  hs, hs+256, hs+512, hs+768, ws, u, hn);
    #pragma unroll
    for (int bb = 0; bb < 4; bb++) {
        float r = sigm_f(gr[bb] + hr[bb]);
        float z = sigm_f(gz[bb] + hz[bb]);
        float n = tanh_f(gn[bb] + r * hn[bb]);
        float dv = (1.f - z) * n + z * hs[bb * 256 + u];
        dts[bb * 256 + u] = dv;
        int gi = (b0 + bb) * UDIM + u;
        g_dt[gi] = dv;
        out_dt[gi] = dv;
    }
    float q[4] = {0.f, 0.f, 0.f, 0.f};
    mv4b(W2, UDIM, dts, dts+256, dts+512, dts+768, ws, u, q);
    #pragma unroll
    for (int bb = 0; bb < 4; bb++) g_query[(b0 + bb) * UDIM + u] = q[bb];
}

// ===== K1: mma.sync fp16x2 keys-GEMM + tanh scores + online softmax + context =====
// Structure identical to R10-proven k1; chains reduced to 2 (Ah*Bh + Al*Bh), B = single fp16.
#define A_STRIDE_B 528
#define B_STRIDE_B 176
#define K1_SCORES 16
#define K1_SCP   528
#define K1_ES    2576
#define K1_QS    3088
#define K1_VS    4112
#define K1_AH    7168
#define K1_AL    74752
#define K1_BH    142336
#define K1_BL    187392
#define K1_SMEM  232448

__global__ __launch_bounds__(512, 1) void k1_mma(
    const float* __restrict__ memory, const float* __restrict__ vvec)
{
    extern __shared__ char smc[];
    float* st = (float*)(smc + 0);
    float* scores_s = (float*)(smc + K1_SCORES);
    float* scp = (float*)(smc + K1_SCP);
    float* e_s = (float*)(smc + K1_ES);
    float* q_s = (float*)(smc + K1_QS);
    float* v_s = (float*)(smc + K1_VS);
    float* ctx_s = (float*)(smc + K1_BL);    // unused region (no Bl image)
    char* AH = smc + K1_AH;
    char* AL = smc + K1_AL;
    uint32_t sb = smem_u32(smc);

    int tid = threadIdx.x, b = blockIdx.x, wid = tid >> 5, lane = tid & 31;
    int warpM = wid & 3, warpN = wid >> 2;
    int uu = tid & 255, half = tid >> 8;
    int m_lane = warpM * 32 + (lane & 7) + ((lane >> 3) & 1) * 8;
    int kA_off = (lane >> 4) * 8;
    uint32_t aBaseH = sb + K1_AH + m_lane * A_STRIDE_B + kA_off * 2;
    uint32_t aBaseL = aBaseH + (K1_AL - K1_AH);
    int n_lane = warpN * 64 + (lane & 7) + ((lane >> 4) & 1) * 8;
    int kB_off = ((lane >> 3) & 1) * 8;
    uint32_t bBaseH = sb + K1_BH + n_lane * B_STRIDE_B + kB_off * 2;

    for (int i = tid; i < 256; i += 512) { q_s[i] = g_query[b * UDIM + i]; v_s[i] = vvec[i]; }
    if (tid == 0) { st[0] = -1e30f; st[1] = 0.f; st[2] = 0.f; }

    float ctx = 0.f, srun = 0.f;
    const float* memb = memory + (size_t)b * TLEN * UDIM;

    for (int tile = 0; tile < 8; tile++) {
        __syncthreads();
        // --- stage A: fp32 -> fp16 hi/lo padded rows ---
        #pragma unroll
        for (int it = 0; it < 16; it++) {
            int idx = tid + it * 512;
            int t = idx >> 6, ug = idx & 63;
            float4 w = *(const float4*)(memb + (size_t)(tile * 128 + t) * UDIM + ug * 4);
            __half hx = __float2half_rn(w.x), hy = __float2half_rn(w.y);
            __half hz = __float2half_rn(w.z), hw = __float2half_rn(w.w);
            __half lx = __float2half_rn(w.x - __half2float(hx));
            __half ly = __float2half_rn(w.y - __half2float(hy));
            __half lz = __float2half_rn(w.z - __half2float(hz));
            __half lw = __float2half_rn(w.w - __half2float(hw));
            uint32_t h0 = ((uint32_t)__half_as_ushort(hy) << 16) | __half_as_ushort(hx);
            uint32_t h1 = ((uint32_t)__half_as_ushort(hw) << 16) | __half_as_ushort(hz);
            uint32_t l0 = ((uint32_t)__half_as_ushort(ly) << 16) | __half_as_ushort(lx);
            uint32_t l1 = ((uint32_t)__half_as_ushort(lw) << 16) | __half_as_ushort(lz);
            int off = t * A_STRIDE_B + ug * 8;
            *(uint2*)(AH + off) = make_uint2(h0, h1);
            *(uint2*)(AL + off) = make_uint2(l0, l1);
        }

        float acc[2][8][4];
        #pragma unroll
        for (int mi = 0; mi < 2; mi++)
            #pragma unroll
            for (int nj = 0; nj < 8; nj++)
                #pragma unroll
                for (int r = 0; r < 4; r++) acc[mi][nj][r] = 0.f;

        for (int c = 0; c < 4; c++) {
            __syncthreads();
            // --- stage B chunk (single fp16 image): 256 n x 64 k = 32KB ---
            #pragma unroll
            for (int it = 0; it < 4; it++) {
                int idx = tid + it * 512;
                int n = idx >> 3, kg = idx & 7;
                uint4 vh = *(const uint4*)((const char*)g_W1f + n * 512 + c * 128 + kg * 16);
                *(uint4*)(smc + K1_BH + n * B_STRIDE_B + kg * 16) = vh;
            }
            __syncthreads();
            #pragma unroll
            for (int ks = 0; ks < 4; ks++) {
                int kg2 = (c * 64 + ks * 16) * 2;
                uint32_t bfr[8][2], ah[2][4], al[2][4];
                #pragma unroll
                for (int ng = 0; ng < 4; ng++) {
                    uint32_t r[4];
                    ldsm_x4(r, bBaseH + ng * (16 * B_STRIDE_B) + ks * 32);
                    bfr[2*ng][0] = r[0]; bfr[2*ng][1] = r[1];
                    bfr[2*ng+1][0] = r[2]; bfr[2*ng+1][1] = r[3];
                }
                ldsm_x4(ah[0], aBaseH + kg2);
                ldsm_x4(ah[1], aBaseH + kg2 + 16 * A_STRIDE_B);
                #pragma unroll
                for (int mi = 0; mi < 2; mi++)
                    #pragma unroll
                    for (int nj = 0; nj < 8; nj++) mma_f16(acc[mi][nj], ah[mi], bfr[nj]);
                ldsm_x4(al[0], aBaseL + kg2);
                ldsm_x4(al[1], aBaseL + kg2 + 16 * A_STRIDE_B);
                #pragma unroll
                for (int mi = 0; mi < 2; mi++)
                    #pragma unroll
                    for (int nj = 0; nj < 8; nj++) mma_f16(acc[mi][nj], al[mi], bfr[nj]);
            }
        }

        // --- scores epilogue ---
        {
            int lq = lane >> 2, lr = lane & 3;
            #pragma unroll
            for (int mi = 0; mi < 2; mi++) {
                float s0 = 0.f, s1 = 0.f;
                #pragma unroll
                for (int nj = 0; nj < 8; nj++) {
                    int n0 = warpN * 64 + nj * 8 + lr * 2;
                    float q0 = q_s[n0], q1 = q_s[n0 + 1];
                    float v0 = v_s[n0], v1 = v_s[n0 + 1];
                    s0 = fmaf(v0, tanh_f(acc[mi][nj][0] + q0), s0);
                    s0 = fmaf(v1, tanh_f(acc[mi][nj][1] + q1), s0);
                    s1 = fmaf(v0, tanh_f(acc[mi][nj][2] + q0), s1);
                    s1 = fmaf(v1, tanh_f(acc[mi][nj][3] + q1), s1);
                }
                s0 += __shfl_xor_sync(0xffffffffu, s0, 1);
                s0 += __shfl_xor_sync(0xffffffffu, s0, 2);
                s1 += __shfl_xor_sync(0xffffffffu, s1, 1);
                s1 += __shfl_xor_sync(0xffffffffu, s1, 2);
                if (lr == 0) {
                    int r0 = warpM * 32 + mi * 16 + lq;
                    scp[warpN * 128 + r0] = s0;
                    scp[warpN * 128 + r0 + 8] = s1;
                }
            }
        }
        __syncthreads();
        if (tid < 128)
            scores_s[tid] = (scp[tid] + scp[128 + tid]) + (scp[256 + tid] + scp[384 + tid]);
        __syncthreads();
        if (tid < 32) {
            float mx = fmaxf(fmaxf(scores_s[tid], scores_s[tid + 32]),
                             fmaxf(scores_s[tid + 64], scores_s[tid + 96]));
            #pragma unroll
            for (int off = 16; off > 0; off >>= 1)
                mx = fmaxf(mx, __shfl_xor_sync(0xffffffffu, mx, off));
            if (tid == 0) {
                float m_old = st[0];
                float m_new = fmaxf(m_old, mx);
                st[2] = ex2f((m_old - m_new) * LOG2E);
                st[0] = m_new;
            }
        }
        __syncthreads();
        float scale = st[2];
        float m_new = st[0];
        ctx *= scale;
        if (tid < 128) {
            float e = ex2f((scores_s[tid] - m_new) * LOG2E);
            e_s[tid] = e;
            srun = srun * scale + e;
        }
        __syncthreads();
        // --- context: ctx[u] += sum_t e[t] * (AH[t][u] + AL[t][u]) ---
        int tstart = half * 64;
        #pragma unroll 4
        for (int t = 0; t < 64; t++) {
            int tt = tstart + t;
            int off = tt * A_STRIDE_B + uu * 2;
            unsigned short ha = *(unsigned short*)(AH + off);
            unsigned short la = *(unsigned short*)(AL + off);
            float fa, fl;
            asm("cvt.f32.f16 %0, %1;" : "=f"(fa) : "h"(ha));
            asm("cvt.f32.f16 %0, %1;" : "=f"(fl) : "h"(la));
            ctx = fmaf(e_s[tt], fa + fl, ctx);
        }
    }

    __syncthreads();
    if (tid < 128) scores_s[tid] = srun;
    ctx_s[half * 256 + uu] = ctx;
    __syncthreads();
    if (tid < 32) {
        float s = scores_s[tid] + scores_s[tid + 32] + scores_s[tid + 64] + scores_s[tid + 96];
        #pragma unroll
        for (int off = 16; off > 0; off >>= 1)
            s += __shfl_xor_sync(0xffffffffu, s, off);
        if (tid == 0) st[1] = s;
    }
    __syncthreads();
    float rinv = 1.f / st[1];
    if (tid < 256) g_ctx[b * UDIM + tid] = (ctx_s[tid] + ctx_s[256 + tid]) * rinv;
}

// ===== K2 (unchanged; proven) =====
#define K2_CAT   0
#define K2_GI    (K2_CAT + 4 * 512)
#define K2_H1    (K2_GI + 4 * 256)
#define K2_H2    (K2_H1 + 4 * 256)
#define K2_G2IN  (K2_H2 + 4 * 256)
#define K2_BF    (K2_G2IN + 4 * 256)
#define K2_WS    (K2_BF + 4 * 256)
#define K2_SMEM_FLOATS (K2_WS + 2 * WS2_HALF)
__global__ __launch_bounds__(256) void k2_tail(
    const float* __restrict__ h1in, const float* __restrict__ h2in,
    const float* __restrict__ g1_Wih, const float* __restrict__ g1_Whh,
    const float* __restrict__ g1_bih, const float* __restrict__ g1_bhh,
    const float* __restrict__ g2_Wih, const float* __restrict__ g2_Whh,
    const float* __restrict__ g2_bih, const float* __restrict__ g2_bhh,
    const float* __restrict__ proj_W, const float* __restrict__ proj_b,
    const float* __restrict__ out_W, const float* __restrict__ out_b,
    float* __restrict__ out_all)
{
    extern __shared__ float sm[];
    float* cat = sm + K2_CAT; float* gi = sm + K2_GI; float* h1s = sm + K2_H1; float* h2s = sm + K2_H2;
    float* g2in = sm + K2_G2IN; float* bfs = sm + K2_BF; float* ws = sm + K2_WS;
    int u = threadIdx.x;
    int b0 = blockIdx.x * 4;
    for (int idx = u; idx < 4 * UDIM; idx += 256) {
        int bb = idx >> 8, j = idx & 255;
        cat[bb * 512 + j] = g_dt[(b0 + bb) * UDIM + j];
        cat[bb * 512 + UDIM + j] = g_ctx[(b0 + bb) * UDIM + j];
        h1s[bb * 256 + j] = h1in[(b0 + bb) * UDIM + j];
        h2s[bb * 256 + j] = h2in[(b0 + bb) * UDIM + j];
    }
    {
        float pb = proj_b[u];
        float a[4] = {pb, pb, pb, pb};
        mv4b(proj_W, 2 * UDIM, cat, cat + 512, cat + 1024, cat + 1536, ws, u, a);
        gi[u] = a[0]; gi[256 + u] = a[1]; gi[512 + u] = a[2]; gi[768 + u] = a[3];
    }
    {
        float gr[4], gz[4], gn[4], hr[4], hz[4], hn[4];
        float br = g1_bih[u], bz = g1_bih[UDIM + u], bn = g1_bih[2 * UDIM + u];
        float cr = g1_bhh[u], cz = g1_bhh[UDIM + u], cn = g1_bhh[2 * UDIM + u];
        #pragma unroll
        for (int bb = 0; bb < 4; bb++) { gr[bb]=br; gz[bb]=bz; gn[bb]=bn; hr[bb]=cr; hz[bb]=cz; hn[bb]=cn; }
        mv4b(g1_Wih,                 UDIM, gi, gi+256, gi+512, gi+768, ws, u, gr);
        mv4b(g1_Wih + UDIM*UDIM,     UDIM, gi, gi+256, gi+512, gi+768, ws, u, gz);
        mv4b(g1_Wih + 2*UDIM*UDIM,   UDIM, gi, gi+256, gi+512, gi+768, ws, u, gn);
        mv4b(g1_Whh,                 UDIM, h1s, h1s+256, h1s+512, h1s+768, ws, u, hr);
        mv4b(g1_Whh + UDIM*UDIM,     UDIM, h1s, h1s+256, h1s+512, h1s+768, ws, u, hz);
        mv4b(g1_Whh + 2*UDIM*UDIM,   UDIM, h1s, h1s+256, h1s+512, h1s+768, ws, u, hn);
        #pragma unroll
        for (int bb = 0; bb < 4; bb++) {
            float r = sigm_f(gr[bb] + hr[bb]);
            float z = sigm_f(gz[bb] + hz[bb]);
            float n = tanh_f(gn[bb] + r * hn[bb]);
            float hnew = (1.f - z) * n + z * h1s[bb * 256 + u];
            out_all[OFF_G1 + (b0 + bb) * UDIM + u] = hnew;
            g2in[bb * 256 + u] = gi[bb * 256 + u] + hnew;
        }
    }
    {
        float gr[4], gz[4], gn[4], hr[4], hz[4], hn[4];
        float br = g2_bih[u], bz = g2_bih[UDIM + u], bn = g2_bih[2 * UDIM + u];
        float cr = g2_bhh[u], cz = g2_bhh[UDIM + u], cn = g2_bhh[2 * UDIM + u];
        #pragma unroll
        for (int bb = 0; bb < 4; bb++) { gr[bb]=br; gz[bb]=bz; gn[bb]=bn; hr[bb]=cr; hz[bb]=cz; hn[bb]=cn; }
        mv4b(g2_Wih,                 UDIM, g2in, g2in+256, g2in+512, g2in+768, ws, u, gr);
        mv4b(g2_Wih + UDIM*UDIM,     UDIM, g2in, g2in+256, g2in+512, g2in+768, ws, u, gz);
        mv4b(g2_Wih + 2*UDIM*UDIM,   UDIM, g2in, g2in+256, g2in+512, g2in+768, ws, u, gn);
        mv4b(g2_Whh,                 UDIM, h2s, h2s+256, h2s+512, h2s+768, ws, u, hr);
        mv4b(g2_Whh + UDIM*UDIM,     UDIM, h2s, h2s+256, h2s+512, h2s+768, ws, u, hz);
        mv4b(g2_Whh + 2*UDIM*UDIM,   UDIM, h2s, h2s+256, h2s+512, h2s+768, ws, u, hn);
        #pragma unroll
        for (int bb = 0; bb < 4; bb++) {
            float r = sigm_f(gr[bb] + hr[bb]);
            float z = sigm_f(gz[bb] + hz[bb]);
            float n = tanh_f(gn[bb] + r * hn[bb]);
            float hnew = (1.f - z) * n + z * h2s[bb * 256 + u];
            out_all[OFF_G2 + (b0 + bb) * UDIM + u] = hnew;
            bfs[bb * 256 + u] = g2in[bb * 256 + u] + hnew;
        }
    }
    __syncthreads();
    for (int o = u; o < OUTD; o += 256) {
        float ob = out_b[o];
        float a0 = ob, a1 = ob, a2 = ob, a3 = ob;
        const float4* w4 = (const float4*)(out_W + o * UDIM);
        #pragma unroll 8
        for (int j4 = 0; j4 < 64; j4++) {
            float4 w = w4[j4];
            int j = j4 * 4;
            a0 = fmaf(bfs[j], w.x, fmaf(bfs[j+1], w.y, fmaf(bfs[j+2], w.z, fmaf(bfs[j+3], w.w, a0))));
            a1 = fmaf(bfs[256+j], w.x, fmaf(bfs[257+j], w.y, fmaf(bfs[258+j], w.z, fmaf(bfs[259+j], w.w, a1))));
            a2 = fmaf(bfs[512+j], w.x, fmaf(bfs[513+j], w.y, fmaf(bfs[514+j], w.z, fmaf(bfs[515+j], w.w, a2))));
            a3 = fmaf(bfs[768+j], w.x, fmaf(bfs[769+j], w.y, fmaf(bfs[770+j], w.z, fmaf(bfs[771+j], w.w, a3))));
        }
        out_all[(b0 + 0) * OUTD + o] = a0;
        out_all[(b0 + 1) * OUTD + o] = a1;
        out_all[(b0 + 2) * OUTD + o] = a2;
        out_all[(b0 + 3) * OUTD + o] = a3;
    }
}

extern "C" void kernel_launch(void* const* d_in, const int* in_sizes, int n_in,
                              void* d_out, int out_size) {
    const float* decoder_input = (const float*)d_in[0];
    const float* memory        = (const float*)d_in[1];
    const float* attn_hidden   = (const float*)d_in[2];
    const float* gru1_hidden   = (const float*)d_in[3];
    const float* gru2_hidden   = (const float*)d_in[4];
    const float* W1            = (const float*)d_in[5];
    const float* W2            = (const float*)d_in[6];
    const float* v             = (const float*)d_in[7];
    const float* attn_Wih      = (const float*)d_in[8];
    const float* attn_Whh      = (const float*)d_in[9];
    const float* attn_bih      = (const float*)d_in[10];
    const float* attn_bhh      = (const float*)d_in[11];
    const float* g1_Wih        = (const float*)d_in[12];
    const float* g1_Whh        = (const float*)d_in[13];
    const float* g1_bih        = (const float*)d_in[14];
    const float* g1_bhh        = (const float*)d_in[15];
    const float* g2_Wih        = (const float*)d_in[16];
    const float* g2_Whh        = (const float*)d_in[17];
    const float* g2_bih        = (const float*)d_in[18];
    const float* g2_bhh        = (const float*)d_in[19];
    const float* proj_W        = (const float*)d_in[20];
    const float* proj_b        = (const float*)d_in[21];
    const float* out_W         = (const float*)d_in[22];
    const float* out_b         = (const float*)d_in[23];
    float* out = (float*)d_out;

    int k0_smem = K0_SMEM_FLOATS * sizeof(float);
    int k2_smem = K2_SMEM_FLOATS * sizeof(float);
    cudaFuncSetAttribute(k0_attn_gru, cudaFuncAttributeMaxDynamicSharedMemorySize, k0_smem);
    cudaFuncSetAttribute(k1_mma, cudaFuncAttributeMaxDynamicSharedMemorySize, K1_SMEM);
    cudaFuncSetAttribute(k2_tail, cudaFuncAttributeMaxDynamicSharedMemorySize, k2_smem);

    kW1prep<<<256, 256>>>(W1);
    k0_attn_gru<<<32, 256, k0_smem>>>(decoder_input, attn_hidden,
                                      attn_Wih, attn_Whh, attn_bih, attn_bhh,
                                      W2, out + OFF_DT);
    k1_mma<<<128, 512, K1_SMEM>>>(memory, v);
    k2_tail<<<32, 256, k2_smem>>>(gru1_hidden, gru2_hidden,
                                  g1_Wih, g1_Whh, g1_bih, g1_bhh,
                                  g2_Wih, g2_Whh, g2_bih, g2_bhh,
                                  proj_W, proj_b, out_W, out_b, out);
}

// round 15
// speedup vs baseline: 6.6376x; 1.0996x over previous
#include <cuda_runtime.h>
#include <cuda_fp16.h>
#include <cstdint>

#define UDIM 256
#define INDIM 128
#define BATCH 128
#define TLEN 1024
#define OUTD 400
#define OFF_DT   51200
#define OFF_G1   83968
#define OFF_G2   116736
#define LOG2E 1.4426950408889634f

typedef unsigned long long ull;

__device__ float g_dt[BATCH * UDIM];
__device__ float g_query[BATCH * UDIM];
__device__ float g_ctx[BATCH * UDIM];
__device__ __align__(16) __half g_W1f[UDIM * UDIM];   // [n][k] fp16

__device__ __forceinline__ float ex2f(float x) {
    float r; asm("ex2.approx.f32 %0, %1;" : "=f"(r) : "f"(x)); return r;
}
__device__ __forceinline__ float rcpf(float x) {
    float r; asm("rcp.approx.f32 %0, %1;" : "=f"(r) : "f"(x)); return r;
}
__device__ __forceinline__ float tanh_f(float x) {
    float xc = fminf(fmaxf(x, -10.f), 10.f);
    float e = ex2f(xc * 2.885390081777927f);
    return (e - 1.f) * rcpf(e + 1.f);
}
__device__ __forceinline__ float sigm_f(float x) {
    float xc = fminf(fmaxf(x, -30.f), 30.f);
    float e = ex2f(-LOG2E * xc);
    return rcpf(1.f + e);
}
__device__ __forceinline__ uint32_t smem_u32(const void* p) {
    uint32_t a;
    asm("{ .reg .u64 t; cvta.to.shared.u64 t, %1; cvt.u32.u64 %0, t; }" : "=r"(a) : "l"(p));
    return a;
}
__device__ __forceinline__ void ldsm_x4(uint32_t r[4], uint32_t addr) {
    asm volatile("ldmatrix.sync.aligned.m8n8.x4.shared.b16 {%0,%1,%2,%3}, [%4];"
        : "=r"(r[0]), "=r"(r[1]), "=r"(r[2]), "=r"(r[3]) : "r"(addr));
}
__device__ __forceinline__ void mma_f16(float d[4], const uint32_t a[4], const uint32_t b[2]) {
    asm volatile("mma.sync.aligned.m16n8k16.row.col.f32.f16.f16.f32 "
        "{%0,%1,%2,%3}, {%4,%5,%6,%7}, {%8,%9}, {%0,%1,%2,%3};"
        : "+f"(d[0]), "+f"(d[1]), "+f"(d[2]), "+f"(d[3])
        : "r"(a[0]), "r"(a[1]), "r"(a[2]), "r"(a[3]), "r"(b[0]), "r"(b[1]));
}

// ===== kW1prep: W1 fp32 -> fp16 linear [n][k] (one-time) =====
__global__ __launch_bounds__(256) void kW1prep(const float* __restrict__ W1) {
    int idx = blockIdx.x * 256 + threadIdx.x;
    g_W1f[idx] = __float2half_rn(W1[idx]);
}

// ===== mv4c: batched matvec, 256 threads, 4 batches, 64-k pairs per barrier =====
// Same staging layout/bank pattern as the proven mv4b, but two 32-k chunks are
// staged + computed per __syncthreads, halving the number of serial latency events.
#define WSC_STRIDE 36
#define WSC_CH (256 * WSC_STRIDE)      // 9216 floats per 32-k chunk
#define WSC_BUF (2 * WSC_CH)           // one 64-k pair buffer
#define WSC_TOTAL (2 * WSC_BUF)        // double-buffered pairs: 36864 floats

__device__ __forceinline__ void mv4c(
    const float* __restrict__ W, int K,   // K multiple of 64
    const float* __restrict__ i0, const float* __restrict__ i1,
    const float* __restrict__ i2, const float* __restrict__ i3,
    float* __restrict__ ws, int tid, float acc[4])
{
    int uu = tid >> 3, kc = tid & 7;
    int npairs = K >> 6;
    float4 pf0[8], pf1[8];
    #pragma unroll
    for (int it = 0; it < 8; it++) {
        pf0[it] = *(const float4*)(W + (uu + 32 * it) * K + kc * 4);
        pf1[it] = *(const float4*)(W + (uu + 32 * it) * K + 32 + kc * 4);
    }
    for (int p = 0; p < npairs; p++) {
        float* wbuf = ws + (p & 1) * WSC_BUF;
        #pragma unroll
        for (int it = 0; it < 8; it++) {
            *(float4*)(wbuf + (uu + 32 * it) * WSC_STRIDE + kc * 4) = pf0[it];
            *(float4*)(wbuf + WSC_CH + (uu + 32 * it) * WSC_STRIDE + kc * 4) = pf1[it];
        }
        __syncthreads();
        if (p + 1 < npairs) {
            int ktn = (p + 1) << 6;
            #pragma unroll
            for (int it = 0; it < 8; it++) {
                pf0[it] = *(const float4*)(W + (uu + 32 * it) * K + ktn + kc * 4);
                pf1[it] = *(const float4*)(W + (uu + 32 * it) * K + ktn + 32 + kc * 4);
            }
        }
        int kt = p << 6;
        const float* wrow0 = wbuf + tid * WSC_STRIDE;
        const float* wrow1 = wbuf + WSC_CH + tid * WSC_STRIDE;
        #pragma unroll
        for (int kk = 0; kk < 8; kk++) {
            float4 w  = *(const float4*)(wrow0 + kk * 4);
            float4 a0 = *(const float4*)(i0 + kt + kk * 4);
            float4 a1 = *(const float4*)(i1 + kt + kk * 4);
            float4 a2 = *(const float4*)(i2 + kt + kk * 4);
            float4 a3 = *(const float4*)(i3 + kt + kk * 4);
            acc[0] = fmaf(a0.x, w.x, fmaf(a0.y, w.y, fmaf(a0.z, w.z, fmaf(a0.w, w.w, acc[0]))));
            acc[1] = fmaf(a1.x, w.x, fmaf(a1.y, w.y, fmaf(a1.z, w.z, fmaf(a1.w, w.w, acc[1]))));
            acc[2] = fmaf(a2.x, w.x, fmaf(a2.y, w.y, fmaf(a2.z, w.z, fmaf(a2.w, w.w, acc[2]))));
            acc[3] = fmaf(a3.x, w.x, fmaf(a3.y, w.y, fmaf(a3.z, w.z, fmaf(a3.w, w.w, acc[3]))));
        }
        #pragma unroll
        for (int kk = 0; kk < 8; kk++) {
            float4 w  = *(const float4*)(wrow1 + kk * 4);
            float4 a0 = *(const float4*)(i0 + kt + 32 + kk * 4);
            float4 a1 = *(const float4*)(i1 + kt + 32 + kk * 4);
            float4 a2 = *(const float4*)(i2 + kt + 32 + kk * 4);
            float4 a3 = *(const float4*)(i3 + kt + 32 + kk * 4);
            acc[0] = fmaf(a0.x, w.x, fmaf(a0.y, w.y, fmaf(a0.z, w.z, fmaf(a0.w, w.w, acc[0]))));
            acc[1] = fmaf(a1.x, w.x, fmaf(a1.y, w.y, fmaf(a1.z, w.z, fmaf(a1.w, w.w, acc[1]))));
            acc[2] = fmaf(a2.x, w.x, fmaf(a2.y, w.y, fmaf(a2.z, w.z, fmaf(a2.w, w.w, acc[2]))));
            acc[3] = fmaf(a3.x, w.x, fmaf(a3.y, w.y, fmaf(a3.z, w.z, fmaf(a3.w, w.w, acc[3]))));
        }
    }
}

// ===== K0: attention GRU cell + query (monolithic, proven structure) =====
#define K0_XS   0
#define K0_HS   (K0_XS + 4 * INDIM)
#define K0_DTS  (K0_HS + 4 * UDIM)
#define K0_WS   (K0_DTS + 4 * UDIM)
#define K0_SMEM_FLOATS (K0_WS + WSC_TOTAL)
__global__ __launch_bounds__(256) void k0_attn_gru(
    const float* __restrict__ x, const float* __restrict__ h,
    const float* __restrict__ Wih, const float* __restrict__ Whh,
    const float* __restrict__ bih, const float* __restrict__ bhh,
    const float* __restrict__ W2, float* __restrict__ out_dt)
{
    extern __shared__ float sm[];
    float* xs = sm + K0_XS; float* hs = sm + K0_HS; float* dts = sm + K0_DTS; float* ws = sm + K0_WS;
    int u = threadIdx.x;
    int b0 = blockIdx.x * 4;
    for (int idx = u; idx < 4 * INDIM; idx += 256) xs[idx] = x[b0 * INDIM + idx];
    for (int idx = u; idx < 4 * UDIM; idx += 256)  hs[idx] = h[b0 * UDIM + idx];
    float gr[4], gz[4], gn[4], hr[4], hz[4], hn[4];
    {
        float br = bih[u], bz = bih[UDIM + u], bn = bih[2 * UDIM + u];
        float cr = bhh[u], cz = bhh[UDIM + u], cn = bhh[2 * UDIM + u];
        #pragma unroll
        for (int bb = 0; bb < 4; bb++) { gr[bb]=br; gz[bb]=bz; gn[bb]=bn; hr[bb]=cr; hz[bb]=cz; hn[bb]=cn; }
    }
    mv4c(Wih,                    INDIM, xs, xs+128, xs+256, xs+384, ws, u, gr);
    mv4c(Wih + UDIM*INDIM,       INDIM, xs, xs+128, xs+256, xs+384, ws, u, gz);
    mv4c(Wih + 2*UDIM*INDIM,     INDIM, xs, xs+128, xs+256, xs+384, ws, u, gn);
    mv4c(Whh,                    UDIM,  hs, hs+256, hs+512, hs+768, ws, u, hr);
    mv4c(Whh + UDIM*UDIM,        UDIM,  hs, hs+256, hs+512, hs+768, ws, u, hz);
    mv4c(Whh + 2*UDIM*UDIM,      UDIM,  hs, hs+256, hs+512, hs+768, ws, u, hn);
    #pragma unroll
    for (int bb = 0; bb < 4; bb++) {
        float r = sigm_f(gr[bb] + hr[bb]);
        float z = sigm_f(gz[bb] + hz[bb]);
        float n = tanh_f(gn[bb] + r * hn[bb]);
        float dv = (1.f - z) * n + z * hs[bb * 256 + u];
        dts[bb * 256 + u] = dv;
        int gi = (b0 + bb) * UDIM + u;
        g_dt[gi] = dv;
        out_dt[gi] = dv;
    }
    float q[4] = {0.f, 0.f, 0.f, 0.f};
    mv4c(W2, UDIM, dts, dts+256, dts+512, dts+768, ws, u, q);
    #pragma unroll
    for (int bb = 0; bb < 4; bb++) g_query[(b0 + bb) * UDIM + u] = q[bb];
}

// ===== K1: mma.sync fp16x2 keys-GEMM + scores + online softmax + context (proven R13) =====
#define A_STRIDE_B 528
#define B_STRIDE_B 176
#define K1_SCORES 16
#define K1_SCP   528
#define K1_ES    2576
#define K1_QS    3088
#define K1_VS    4112
#define K1_AH    7168
#define K1_AL    74752
#define K1_BH    142336
#define K1_BL    187392
#define K1_SMEM  232448

__global__ __launch_bounds__(512, 1) void k1_mma(
    const float* __restrict__ memory, const float* __restrict__ vvec)
{
    extern __shared__ char smc[];
    float* st = (float*)(smc + 0);
    float* scores_s = (float*)(smc + K1_SCORES);
    float* scp = (float*)(smc + K1_SCP);
    float* e_s = (float*)(smc + K1_ES);
    float* q_s = (float*)(smc + K1_QS);
    float* v_s = (float*)(smc + K1_VS);
    float* ctx_s = (float*)(smc + K1_BL);
    char* AH = smc + K1_AH;
    char* AL = smc + K1_AL;
    uint32_t sb = smem_u32(smc);

    int tid = threadIdx.x, b = blockIdx.x, wid = tid >> 5, lane = tid & 31;
    int warpM = wid & 3, warpN = wid >> 2;
    int uu = tid & 255, half = tid >> 8;
    int m_lane = warpM * 32 + (lane & 7) + ((lane >> 3) & 1) * 8;
    int kA_off = (lane >> 4) * 8;
    uint32_t aBaseH = sb + K1_AH + m_lane * A_STRIDE_B + kA_off * 2;
    uint32_t aBaseL = aBaseH + (K1_AL - K1_AH);
    int n_lane = warpN * 64 + (lane & 7) + ((lane >> 4) & 1) * 8;
    int kB_off = ((lane >> 3) & 1) * 8;
    uint32_t bBaseH = sb + K1_BH + n_lane * B_STRIDE_B + kB_off * 2;

    for (int i = tid; i < 256; i += 512) { q_s[i] = g_query[b * UDIM + i]; v_s[i] = vvec[i]; }
    if (tid == 0) { st[0] = -1e30f; st[1] = 0.f; st[2] = 0.f; }

    float ctx = 0.f, srun = 0.f;
    const float* memb = memory + (size_t)b * TLEN * UDIM;

    for (int tile = 0; tile < 8; tile++) {
        __syncthreads();
        #pragma unroll
        for (int it = 0; it < 16; it++) {
            int idx = tid + it * 512;
            int t = idx >> 6, ug = idx & 63;
            float4 w = *(const float4*)(memb + (size_t)(tile * 128 + t) * UDIM + ug * 4);
            __half hx = __float2half_rn(w.x), hy = __float2half_rn(w.y);
            __half hz = __float2half_rn(w.z), hw = __float2half_rn(w.w);
            __half lx = __float2half_rn(w.x - __half2float(hx));
            __half ly = __float2half_rn(w.y - __half2float(hy));
            __half lz = __float2half_rn(w.z - __half2float(hz));
            __half lw = __float2half_rn(w.w - __half2float(hw));
            uint32_t h0 = ((uint32_t)__half_as_ushort(hy) << 16) | __half_as_ushort(hx);
            uint32_t h1 = ((uint32_t)__half_as_ushort(hw) << 16) | __half_as_ushort(hz);
            uint32_t l0 = ((uint32_t)__half_as_ushort(ly) << 16) | __half_as_ushort(lx);
            uint32_t l1 = ((uint32_t)__half_as_ushort(lw) << 16) | __half_as_ushort(lz);
            int off = t * A_STRIDE_B + ug * 8;
            *(uint2*)(AH + off) = make_uint2(h0, h1);
            *(uint2*)(AL + off) = make_uint2(l0, l1);
        }

        float acc[2][8][4];
        #pragma unroll
        for (int mi = 0; mi < 2; mi++)
            #pragma unroll
            for (int nj = 0; nj < 8; nj++)
                #pragma unroll
                for (int r = 0; r < 4; r++) acc[mi][nj][r] = 0.f;

        for (int c = 0; c < 4; c++) {
            __syncthreads();
            #pragma unroll
            for (int it = 0; it < 4; it++) {
                int idx = tid + it * 512;
                int n = idx >> 3, kg = idx & 7;
                uint4 vh = *(const uint4*)((const char*)g_W1f + n * 512 + c * 128 + kg * 16);
                *(uint4*)(smc + K1_BH + n * B_STRIDE_B + kg * 16) = vh;
            }
            __syncthreads();
            #pragma unroll
            for (int ks = 0; ks < 4; ks++) {
                int kg2 = (c * 64 + ks * 16) * 2;
                uint32_t bfr[8][2], ah[2][4], al[2][4];
                #pragma unroll
                for (int ng = 0; ng < 4; ng++) {
                    uint32_t r[4];
                    ldsm_x4(r, bBaseH + ng * (16 * B_STRIDE_B) + ks * 32);
                    bfr[2*ng][0] = r[0]; bfr[2*ng][1] = r[1];
                    bfr[2*ng+1][0] = r[2]; bfr[2*ng+1][1] = r[3];
                }
                ldsm_x4(ah[0], aBaseH + kg2);
                ldsm_x4(ah[1], aBaseH + kg2 + 16 * A_STRIDE_B);
                #pragma unroll
                for (int mi = 0; mi < 2; mi++)
                    #pragma unroll
                    for (int nj = 0; nj < 8; nj++) mma_f16(acc[mi][nj], ah[mi], bfr[nj]);
                ldsm_x4(al[0], aBaseL + kg2);
                ldsm_x4(al[1], aBaseL + kg2 + 16 * A_STRIDE_B);
                #pragma unroll
                for (int mi = 0; mi < 2; mi++)
                    #pragma unroll
                    for (int nj = 0; nj < 8; nj++) mma_f16(acc[mi][nj], al[mi], bfr[nj]);
            }
        }

        {
            int lq = lane >> 2, lr = lane & 3;
            #pragma unroll
            for (int mi = 0; mi < 2; mi++) {
                float s0 = 0.f, s1 = 0.f;
                #pragma unroll
                for (int nj = 0; nj < 8; nj++) {
                    int n0 = warpN * 64 + nj * 8 + lr * 2;
                    float q0 = q_s[n0], q1 = q_s[n0 + 1];
                    float v0 = v_s[n0], v1 = v_s[n0 + 1];
                    s0 = fmaf(v0, tanh_f(acc[mi][nj][0] + q0), s0);
                    s0 = fmaf(v1, tanh_f(acc[mi][nj][1] + q1), s0);
                    s1 = fmaf(v0, tanh_f(acc[mi][nj][2] + q0), s1);
                    s1 = fmaf(v1, tanh_f(acc[mi][nj][3] + q1), s1);
                }
                s0 += __shfl_xor_sync(0xffffffffu, s0, 1);
                s0 += __shfl_xor_sync(0xffffffffu, s0, 2);
                s1 += __shfl_xor_sync(0xffffffffu, s1, 1);
                s1 += __shfl_xor_sync(0xffffffffu, s1, 2);
                if (lr == 0) {
                    int r0 = warpM * 32 + mi * 16 + lq;
                    scp[warpN * 128 + r0] = s0;
                    scp[warpN * 128 + r0 + 8] = s1;
                }
            }
        }
        __syncthreads();
        if (tid < 128)
            scores_s[tid] = (scp[tid] + scp[128 + tid]) + (scp[256 + tid] + scp[384 + tid]);
        __syncthreads();
        if (tid < 32) {
            float mx = fmaxf(fmaxf(scores_s[tid], scores_s[tid + 32]),
                             fmaxf(scores_s[tid + 64], scores_s[tid + 96]));
            #pragma unroll
            for (int off = 16; off > 0; off >>= 1)
                mx = fmaxf(mx, __shfl_xor_sync(0xffffffffu, mx, off));
            if (tid == 0) {
                float m_old = st[0];
                float m_new = fmaxf(m_old, mx);
                st[2] = ex2f((m_old - m_new) * LOG2E);
                st[0] = m_new;
            }
        }
        __syncthreads();
        float scale = st[2];
        float m_new = st[0];
        ctx *= scale;
        if (tid < 128) {
            float e = ex2f((scores_s[tid] - m_new) * LOG2E);
            e_s[tid] = e;
            srun = srun * scale + e;
        }
        __syncthreads();
        int tstart = half * 64;
        #pragma unroll 4
        for (int t = 0; t < 64; t++) {
            int tt = tstart + t;
            int off = tt * A_STRIDE_B + uu * 2;
            unsigned short ha = *(unsigned short*)(AH + off);
            unsigned short la = *(unsigned short*)(AL + off);
            float fa, fl;
            asm("cvt.f32.f16 %0, %1;" : "=f"(fa) : "h"(ha));
            asm("cvt.f32.f16 %0, %1;" : "=f"(fl) : "h"(la));
            ctx = fmaf(e_s[tt], fa + fl, ctx);
        }
    }

    __syncthreads();
    if (tid < 128) scores_s[tid] = srun;
    ctx_s[half * 256 + uu] = ctx;
    __syncthreads();
    if (tid < 32) {
        float s = scores_s[tid] + scores_s[tid + 32] + scores_s[tid + 64] + scores_s[tid + 96];
        #pragma unroll
        for (int off = 16; off > 0; off >>= 1)
            s += __shfl_xor_sync(0xffffffffu, s, off);
        if (tid == 0) st[1] = s;
    }
    __syncthreads();
    float rinv = 1.f / st[1];
    if (tid < 256) g_ctx[b * UDIM + tid] = (ctx_s[tid] + ctx_s[256 + tid]) * rinv;
}

// ===== K2: proj -> GRU1 -> GRU2 -> out (monolithic, proven structure) =====
#define K2_CAT   0
#define K2_GI    (K2_CAT + 4 * 512)
#define K2_H1    (K2_GI + 4 * 256)
#define K2_H2    (K2_H1 + 4 * 256)
#define K2_G2IN  (K2_H2 + 4 * 256)
#define K2_BF    (K2_G2IN + 4 * 256)
#define K2_WS    (K2_BF + 4 * 256)
#define K2_SMEM_FLOATS (K2_WS + WSC_TOTAL)
__global__ __launch_bounds__(256) void k2_tail(
    const float* __restrict__ h1in, const float* __restrict__ h2in,
    const float* __restrict__ g1_Wih, const float* __restrict__ g1_Whh,
    const float* __restrict__ g1_bih, const float* __restrict__ g1_bhh,
    const float* __restrict__ g2_Wih, const float* __restrict__ g2_Whh,
    const float* __restrict__ g2_bih, const float* __restrict__ g2_bhh,
    const float* __restrict__ proj_W, const float* __restrict__ proj_b,
    const float* __restrict__ out_W, const float* __restrict__ out_b,
    float* __restrict__ out_all)
{
    extern __shared__ float sm[];
    float* cat = sm + K2_CAT; float* gi = sm + K2_GI; float* h1s = sm + K2_H1; float* h2s = sm + K2_H2;
    float* g2in = sm + K2_G2IN; float* bfs = sm + K2_BF; float* ws = sm + K2_WS;
    int u = threadIdx.x;
    int b0 = blockIdx.x * 4;
    for (int idx = u; idx < 4 * UDIM; idx += 256) {
        int bb = idx >> 8, j = idx & 255;
        cat[bb * 512 + j] = g_dt[(b0 + bb) * UDIM + j];
        cat[bb * 512 + UDIM + j] = g_ctx[(b0 + bb) * UDIM + j];
        h1s[bb * 256 + j] = h1in[(b0 + bb) * UDIM + j];
        h2s[bb * 256 + j] = h2in[(b0 + bb) * UDIM + j];
    }
    {
        float pb = proj_b[u];
        float a[4] = {pb, pb, pb, pb};
        mv4c(proj_W, 2 * UDIM, cat, cat + 512, cat + 1024, cat + 1536, ws, u, a);
        gi[u] = a[0]; gi[256 + u] = a[1]; gi[512 + u] = a[2]; gi[768 + u] = a[3];
    }
    {
        float gr[4], gz[4], gn[4], hr[4], hz[4], hn[4];
        float br = g1_bih[u], bz = g1_bih[UDIM + u], bn = g1_bih[2 * UDIM + u];
        float cr = g1_bhh[u], cz = g1_bhh[UDIM + u], cn = g1_bhh[2 * UDIM + u];
        #pragma unroll
        for (int bb = 0; bb < 4; bb++) { gr[bb]=br; gz[bb]=bz; gn[bb]=bn; hr[bb]=cr; hz[bb]=cz; hn[bb]=cn; }
        mv4c(g1_Wih,                 UDIM, gi, gi+256, gi+512, gi+768, ws, u, gr);
        mv4c(g1_Wih + UDIM*UDIM,     UDIM, gi, gi+256, gi+512, gi+768, ws, u, gz);
        mv4c(g1_Wih + 2*UDIM*UDIM,   UDIM, gi, gi+256, gi+512, gi+768, ws, u, gn);
        mv4c(g1_Whh,                 UDIM, h1s, h1s+256, h1s+512, h1s+768, ws, u, hr);
        mv4c(g1_Whh + UDIM*UDIM,     UDIM, h1s, h1s+256, h1s+512, h1s+768, ws, u, hz);
        mv4c(g1_Whh + 2*UDIM*UDIM,   UDIM, h1s, h1s+256, h1s+512, h1s+768, ws, u, hn);
        #pragma unroll
        for (int bb = 0; bb < 4; bb++) {
            float r = sigm_f(gr[bb] + hr[bb]);
            float z = sigm_f(gz[bb] + hz[bb]);
            float n = tanh_f(gn[bb] + r * hn[bb]);
            float hnew = (1.f - z) * n + z * h1s[bb * 256 + u];
            out_all[OFF_G1 + (b0 + bb) * UDIM + u] = hnew;
            g2in[bb * 256 + u] = gi[bb * 256 + u] + hnew;
        }
    }
    {
        float gr[4], gz[4], gn[4], hr[4], hz[4], hn[4];
        float br = g2_bih[u], bz = g2_bih[UDIM + u], bn = g2_bih[2 * UDIM + u];
        float cr = g2_bhh[u], cz = g2_bhh[UDIM + u], cn = g2_bhh[2 * UDIM + u];
        #pragma unroll
        for (int bb = 0; bb < 4; bb++) { gr[bb]=br; gz[bb]=bz; gn[bb]=bn; hr[bb]=cr; hz[bb]=cz; hn[bb]=cn; }
        mv4c(g2_Wih,                 UDIM, g2in, g2in+256, g2in+512, g2in+768, ws, u, gr);
        mv4c(g2_Wih + UDIM*UDIM,     UDIM, g2in, g2in+256, g2in+512, g2in+768, ws, u, gz);
        mv4c(g2_Wih + 2*UDIM*UDIM,   UDIM, g2in, g2in+256, g2in+512, g2in+768, ws, u, gn);
        mv4c(g2_Whh,                 UDIM, h2s, h2s+256, h2s+512, h2s+768, ws, u, hr);
        mv4c(g2_Whh + UDIM*UDIM,     UDIM, h2s, h2s+256, h2s+512, h2s+768, ws, u, hz);
        mv4c(g2_Whh + 2*UDIM*UDIM,   UDIM, h2s, h2s+256, h2s+512, h2s+768, ws, u, hn);
        #pragma unroll
        for (int bb = 0; bb < 4; bb++) {
            float r = sigm_f(gr[bb] + hr[bb]);
            float z = sigm_f(gz[bb] + hz[bb]);
            float n = tanh_f(gn[bb] + r * hn[bb]);
            float hnew = (1.f - z) * n + z * h2s[bb * 256 + u];
            out_all[OFF_G2 + (b0 + bb) * UDIM + u] = hnew;
            bfs[bb * 256 + u] = g2in[bb * 256 + u] + hnew;
        }
    }
    __syncthreads();
    for (int o = u; o < OUTD; o += 256) {
        float ob = out_b[o];
        float a0 = ob, a1 = ob, a2 = ob, a3 = ob;
        const float4* w4 = (const float4*)(out_W + o * UDIM);
        #pragma unroll 8
        for (int j4 = 0; j4 < 64; j4++) {
            float4 w = w4[j4];
            int j = j4 * 4;
            a0 = fmaf(bfs[j], w.x, fmaf(bfs[j+1], w.y, fmaf(bfs[j+2], w.z, fmaf(bfs[j+3], w.w, a0))));
            a1 = fmaf(bfs[256+j], w.x, fmaf(bfs[257+j], w.y, fmaf(bfs[258+j], w.z, fmaf(bfs[259+j], w.w, a1))));
            a2 = fmaf(bfs[512+j], w.x, fmaf(bfs[513+j], w.y, fmaf(bfs[514+j], w.z, fmaf(bfs[515+j], w.w, a2))));
            a3 = fmaf(bfs[768+j], w.x, fmaf(bfs[769+j], w.y, fmaf(bfs[770+j], w.z, fmaf(bfs[771+j], w.w, a3))));
        }
        out_all[(b0 + 0) * OUTD + o] = a0;
        out_all[(b0 + 1) * OUTD + o] = a1;
        out_all[(b0 + 2) * OUTD + o] = a2;
        out_all[(b0 + 3) * OUTD + o] = a3;
    }
}

extern "C" void kernel_launch(void* const* d_in, const int* in_sizes, int n_in,
                              void* d_out, int out_size) {
    const float* decoder_input = (const float*)d_in[0];
    const float* memory        = (const float*)d_in[1];
    const float* attn_hidden   = (const float*)d_in[2];
    const float* gru1_hidden   = (const float*)d_in[3];
    const float* gru2_hidden   = (const float*)d_in[4];
    const float* W1            = (const float*)d_in[5];
    const float* W2            = (const float*)d_in[6];
    const float* v             = (const float*)d_in[7];
    const float* attn_Wih      = (const float*)d_in[8];
    const float* attn_Whh      = (const float*)d_in[9];
    const float* attn_bih      = (const float*)d_in[10];
    const float* attn_bhh      = (const float*)d_in[11];
    const float* g1_Wih        = (const float*)d_in[12];
    const float* g1_Whh        = (const float*)d_in[13];
    const float* g1_bih        = (const float*)d_in[14];
    const float* g1_bhh        = (const float*)d_in[15];
    const float* g2_Wih        = (const float*)d_in[16];
    const float* g2_Whh        = (const float*)d_in[17];
    const float* g2_bih        = (const float*)d_in[18];
    const float* g2_bhh        = (const float*)d_in[19];
    const float* proj_W        = (const float*)d_in[20];
    const float* proj_b        = (const float*)d_in[21];
    const float* out_W         = (const float*)d_in[22];
    const float* out_b         = (const float*)d_in[23];
    float* out = (float*)d_out;

    int k0_smem = K0_SMEM_FLOATS * sizeof(float);
    int k2_smem = K2_SMEM_FLOATS * sizeof(float);
    cudaFuncSetAttribute(k0_attn_gru, cudaFuncAttributeMaxDynamicSharedMemorySize, k0_smem);
    cudaFuncSetAttribute(k1_mma, cudaFuncAttributeMaxDynamicSharedMemorySize, K1_SMEM);
    cudaFuncSetAttribute(k2_tail, cudaFuncAttributeMaxDynamicSharedMemorySize, k2_smem);

    kW1prep<<<256, 256>>>(W1);
    k0_attn_gru<<<32, 256, k0_smem>>>(decoder_input, attn_hidden,
                                      attn_Wih, attn_Whh, attn_bih, attn_bhh,
                                      W2, out + OFF_DT);
    k1_mma<<<128, 512, K1_SMEM>>>(memory, v);
    k2_tail<<<32, 256, k2_smem>>>(gru1_hidden, gru2_hidden,
                                  g1_Wih, g1_Whh, g1_bih, g1_bhh,
                                  g2_Wih, g2_Whh, g2_bih, g2_bhh,
                                  proj_W, proj_b, out_W, out_b, out);
}